// round 1
// baseline (speedup 1.0000x reference)
#include <cuda_runtime.h>
#include <cuda_bf16.h>
#include <math.h>

// Problem constants
#define L_SEQ   2048
#define N_BATCH 4
#define EMB     1024
#define NH      16
#define DH      64
#define NHEADS  (N_BATCH * NH)      // 64
#define M_ROWS  (L_SEQ * N_BATCH)   // 8192

// Scratch (allocation-free: __device__ globals)
__device__ float g_q[(size_t)NHEADS * L_SEQ * DH];   // 32 MB, [head, l, d], pre-scaled
__device__ float g_k[(size_t)NHEADS * L_SEQ * DH];   // 32 MB
__device__ float g_v[(size_t)NHEADS * L_SEQ * DH];   // 32 MB
__device__ float g_ctx[(size_t)M_ROWS * EMB];        // 32 MB, [l, n, e]

// ---------------------------------------------------------------------------
// Kernel 1: QKV projection.  C[m, o] = sum_k x[m,k] * Wqkv[o,k]
// M=8192, N=3072, K=1024.  128x128x8 tile, 256 threads, 8x8 per thread.
// Epilogue scatters into g_q/g_k/g_v with head layout; Q pre-scaled by Dh^-0.5.
// ---------------------------------------------------------------------------
__global__ __launch_bounds__(256) void qkv_gemm_kernel(
    const float* __restrict__ A, const float* __restrict__ W)
{
    __shared__ float As[8][128];
    __shared__ float Bs[8][128];

    const int bx = blockIdx.x;   // o tile (24)
    const int by = blockIdx.y;   // m tile (64)
    const int tid = threadIdx.x;
    const int tx = tid & 15;
    const int ty = tid >> 4;
    const int lrow = tid >> 1;          // 0..127
    const int lcol = (tid & 1) * 4;     // 0 or 4

    const float* Ap = A + (size_t)(by * 128 + lrow) * EMB + lcol;
    const float* Wp = W + (size_t)(bx * 128 + lrow) * EMB + lcol;

    float acc[8][8];
#pragma unroll
    for (int i = 0; i < 8; i++)
#pragma unroll
        for (int j = 0; j < 8; j++) acc[i][j] = 0.0f;

    for (int k0 = 0; k0 < EMB; k0 += 8) {
        float4 a4 = *(const float4*)(Ap + k0);
        float4 b4 = *(const float4*)(Wp + k0);
        As[lcol + 0][lrow] = a4.x; As[lcol + 1][lrow] = a4.y;
        As[lcol + 2][lrow] = a4.z; As[lcol + 3][lrow] = a4.w;
        Bs[lcol + 0][lrow] = b4.x; Bs[lcol + 1][lrow] = b4.y;
        Bs[lcol + 2][lrow] = b4.z; Bs[lcol + 3][lrow] = b4.w;
        __syncthreads();
#pragma unroll
        for (int kk = 0; kk < 8; kk++) {
            float a[8], b[8];
#pragma unroll
            for (int i = 0; i < 4; i++) {
                a[i]     = As[kk][ty * 4 + i];
                a[4 + i] = As[kk][64 + ty * 4 + i];
                b[i]     = Bs[kk][tx * 4 + i];
                b[4 + i] = Bs[kk][64 + tx * 4 + i];
            }
#pragma unroll
            for (int i = 0; i < 8; i++)
#pragma unroll
                for (int j = 0; j < 8; j++) acc[i][j] += a[i] * b[j];
        }
        __syncthreads();
    }

    const float scale = 0.125f;  // 64^-0.5
#pragma unroll
    for (int i = 0; i < 8; i++) {
        const int mrow = by * 128 + ((i < 4) ? (ty * 4 + i) : (64 + ty * 4 + i - 4));
        const int l = mrow >> 2;
        const int n = mrow & 3;
#pragma unroll
        for (int j = 0; j < 8; j++) {
            const int o = bx * 128 + ((j < 4) ? (tx * 4 + j) : (64 + tx * 4 + j - 4));
            const int sec = o >> 10;       // 0=q 1=k 2=v (uniform per block)
            const int oo  = o & 1023;
            const int h   = oo >> 6;
            const int d   = oo & 63;
            const size_t idx = ((size_t)(n * NH + h) * L_SEQ + l) * DH + d;
            const float val = acc[i][j];
            if (sec == 0)      g_q[idx] = val * scale;
            else if (sec == 1) g_k[idx] = val;
            else               g_v[idx] = val;
        }
    }
}

// ---------------------------------------------------------------------------
// Kernel 2: causal flash attention. One CTA per (q-tile of 64 rows, head).
// 64x64 key tiles; online softmax; P staged via smem; fp32 throughout.
// ---------------------------------------------------------------------------
#define LDT 65   // padded stride for transposed tiles (scalar stores)
#define LDV 68   // padded stride for V (keeps float4 alignment)
#define ATTN_SMEM_FLOATS (3 * 64 * LDT + 64 * LDV)   // 16832
#define ATTN_SMEM_BYTES  (ATTN_SMEM_FLOATS * 4)      // 67328

__global__ __launch_bounds__(256) void attn_kernel()
{
    extern __shared__ float sm[];
    float* Qs = sm;                 // [d][r], stride LDT
    float* Ks = Qs + 64 * LDT;      // [d][c], stride LDT
    float* Ps = Ks + 64 * LDT;      // [c][r], stride LDT
    float* Vs = Ps + 64 * LDT;      // [c][d], stride LDV

    const int qt   = blockIdx.x;        // 0..31
    const int head = blockIdx.y;        // 0..63
    const int qbase = qt * 64;
    const int tid = threadIdx.x;
    const int tx = tid & 15;
    const int ty = tid >> 4;

    const float* Qg = g_q + (size_t)head * L_SEQ * DH;
    const float* Kg = g_k + (size_t)head * L_SEQ * DH;
    const float* Vg = g_v + (size_t)head * L_SEQ * DH;

    // Load Q tile transposed: Qs[d][r]
#pragma unroll
    for (int rep = 0; rep < 4; rep++) {
        const int idx = tid + rep * 256;   // 0..1023
        const int r  = idx >> 4;
        const int d0 = (idx & 15) * 4;
        float4 q4 = *(const float4*)(Qg + (size_t)(qbase + r) * DH + d0);
        Qs[(d0 + 0) * LDT + r] = q4.x;
        Qs[(d0 + 1) * LDT + r] = q4.y;
        Qs[(d0 + 2) * LDT + r] = q4.z;
        Qs[(d0 + 3) * LDT + r] = q4.w;
    }

    float m_r[4], l_r[4], o_acc[4][4];
#pragma unroll
    for (int i = 0; i < 4; i++) {
        m_r[i] = -1e30f;
        l_r[i] = 0.0f;
#pragma unroll
        for (int j = 0; j < 4; j++) o_acc[i][j] = 0.0f;
    }

    for (int kt = 0; kt <= qt; kt++) {
        const int kbase = kt * 64;
        __syncthreads();   // protect Ks/Vs (and Qs on first iter) before reload
        // Load K transposed + V direct
#pragma unroll
        for (int rep = 0; rep < 4; rep++) {
            const int idx = tid + rep * 256;
            const int c  = idx >> 4;
            const int d0 = (idx & 15) * 4;
            float4 k4 = *(const float4*)(Kg + (size_t)(kbase + c) * DH + d0);
            Ks[(d0 + 0) * LDT + c] = k4.x;
            Ks[(d0 + 1) * LDT + c] = k4.y;
            Ks[(d0 + 2) * LDT + c] = k4.z;
            Ks[(d0 + 3) * LDT + c] = k4.w;
            float4 v4 = *(const float4*)(Vg + (size_t)(kbase + c) * DH + d0);
            *(float4*)(Vs + c * LDV + d0) = v4;
        }
        __syncthreads();

        // S = Q K^T (this thread: rows ty*4+i, cols tx*4+j)
        float s[4][4];
#pragma unroll
        for (int i = 0; i < 4; i++)
#pragma unroll
            for (int j = 0; j < 4; j++) s[i][j] = 0.0f;
#pragma unroll
        for (int d = 0; d < 64; d++) {
            float a[4], b[4];
#pragma unroll
            for (int i = 0; i < 4; i++) a[i] = Qs[d * LDT + ty * 4 + i];
#pragma unroll
            for (int j = 0; j < 4; j++) b[j] = Ks[d * LDT + tx * 4 + j];
#pragma unroll
            for (int i = 0; i < 4; i++)
#pragma unroll
                for (int j = 0; j < 4; j++) s[i][j] += a[i] * b[j];
        }

        // Causal mask (only possible on the diagonal tile: kbase == qbase)
        if (kt == qt) {
#pragma unroll
            for (int i = 0; i < 4; i++)
#pragma unroll
                for (int j = 0; j < 4; j++)
                    if (tx * 4 + j > ty * 4 + i) s[i][j] = -100000.0f;
        }

        // Online softmax update; row groups = 16 consecutive lanes (same ty)
#pragma unroll
        for (int i = 0; i < 4; i++) {
            float mx = s[i][0];
#pragma unroll
            for (int j = 1; j < 4; j++) mx = fmaxf(mx, s[i][j]);
#pragma unroll
            for (int off = 8; off >= 1; off >>= 1)
                mx = fmaxf(mx, __shfl_xor_sync(0xffffffffu, mx, off));
            const float mn = fmaxf(m_r[i], mx);
            const float corr = __expf(m_r[i] - mn);
            m_r[i] = mn;
            l_r[i] *= corr;
#pragma unroll
            for (int j = 0; j < 4; j++) o_acc[i][j] *= corr;
            float rs = 0.0f;
#pragma unroll
            for (int j = 0; j < 4; j++) {
                const float p = __expf(s[i][j] - mn);
                s[i][j] = p;
                rs += p;
            }
#pragma unroll
            for (int off = 8; off >= 1; off >>= 1)
                rs += __shfl_xor_sync(0xffffffffu, rs, off);
            l_r[i] += rs;
        }

        // Stage P transposed: Ps[c][r]
#pragma unroll
        for (int i = 0; i < 4; i++)
#pragma unroll
            for (int j = 0; j < 4; j++)
                Ps[(tx * 4 + j) * LDT + ty * 4 + i] = s[i][j];
        __syncthreads();

        // O += P @ V (this thread: rows ty*4+i, dims tx*4+j)
#pragma unroll
        for (int c = 0; c < 64; c++) {
            float a[4], b[4];
#pragma unroll
            for (int i = 0; i < 4; i++) a[i] = Ps[c * LDT + ty * 4 + i];
#pragma unroll
            for (int j = 0; j < 4; j++) b[j] = Vs[c * LDV + tx * 4 + j];
#pragma unroll
            for (int i = 0; i < 4; i++)
#pragma unroll
                for (int j = 0; j < 4; j++) o_acc[i][j] += a[i] * b[j];
        }
    }

    // Normalize and write to ctx in [L, N, E] layout
    const int n = head >> 4;
    const int h = head & 15;
#pragma unroll
    for (int i = 0; i < 4; i++) {
        const float inv = 1.0f / l_r[i];
        const int l = qbase + ty * 4 + i;
        float4 o4 = make_float4(o_acc[i][0] * inv, o_acc[i][1] * inv,
                                o_acc[i][2] * inv, o_acc[i][3] * inv);
        *(float4*)(g_ctx + ((size_t)l * N_BATCH + n) * EMB + h * DH + tx * 4) = o4;
    }
}

// ---------------------------------------------------------------------------
// Kernel 3: output projection.  out[m, o] = sum_k ctx[m,k] * Wout[o,k]
// M=8192, N=1024, K=1024.  Same 128x128x8 tiling.
// ---------------------------------------------------------------------------
__global__ __launch_bounds__(256) void out_gemm_kernel(
    const float* __restrict__ W, float* __restrict__ C)
{
    __shared__ float As[8][128];
    __shared__ float Bs[8][128];

    const int bx = blockIdx.x;   // o tile (8)
    const int by = blockIdx.y;   // m tile (64)
    const int tid = threadIdx.x;
    const int tx = tid & 15;
    const int ty = tid >> 4;
    const int lrow = tid >> 1;
    const int lcol = (tid & 1) * 4;

    const float* Ap = g_ctx + (size_t)(by * 128 + lrow) * EMB + lcol;
    const float* Wp = W + (size_t)(bx * 128 + lrow) * EMB + lcol;

    float acc[8][8];
#pragma unroll
    for (int i = 0; i < 8; i++)
#pragma unroll
        for (int j = 0; j < 8; j++) acc[i][j] = 0.0f;

    for (int k0 = 0; k0 < EMB; k0 += 8) {
        float4 a4 = *(const float4*)(Ap + k0);
        float4 b4 = *(const float4*)(Wp + k0);
        As[lcol + 0][lrow] = a4.x; As[lcol + 1][lrow] = a4.y;
        As[lcol + 2][lrow] = a4.z; As[lcol + 3][lrow] = a4.w;
        Bs[lcol + 0][lrow] = b4.x; Bs[lcol + 1][lrow] = b4.y;
        Bs[lcol + 2][lrow] = b4.z; Bs[lcol + 3][lrow] = b4.w;
        __syncthreads();
#pragma unroll
        for (int kk = 0; kk < 8; kk++) {
            float a[8], b[8];
#pragma unroll
            for (int i = 0; i < 4; i++) {
                a[i]     = As[kk][ty * 4 + i];
                a[4 + i] = As[kk][64 + ty * 4 + i];
                b[i]     = Bs[kk][tx * 4 + i];
                b[4 + i] = Bs[kk][64 + tx * 4 + i];
            }
#pragma unroll
            for (int i = 0; i < 8; i++)
#pragma unroll
                for (int j = 0; j < 8; j++) acc[i][j] += a[i] * b[j];
        }
        __syncthreads();
    }

#pragma unroll
    for (int i = 0; i < 8; i++) {
        const int mrow = by * 128 + ((i < 4) ? (ty * 4 + i) : (64 + ty * 4 + i - 4));
        float* Crow = C + (size_t)mrow * EMB + bx * 128;
        float4 v0 = make_float4(acc[i][0], acc[i][1], acc[i][2], acc[i][3]);
        float4 v1 = make_float4(acc[i][4], acc[i][5], acc[i][6], acc[i][7]);
        *(float4*)(Crow + tx * 4)      = v0;
        *(float4*)(Crow + 64 + tx * 4) = v1;
    }
}

// ---------------------------------------------------------------------------
extern "C" void kernel_launch(void* const* d_in, const int* in_sizes, int n_in,
                              void* d_out, int out_size)
{
    const float* x    = (const float*)d_in[0];   // [L, N, E]
    const float* wqkv = (const float*)d_in[1];   // [3E, E]
    const float* wout = (const float*)d_in[2];   // [E, E]
    // d_in[3] = mask — causal, implemented analytically
    float* out = (float*)d_out;                  // [L, N, E]

    cudaFuncSetAttribute(attn_kernel,
                         cudaFuncAttributeMaxDynamicSharedMemorySize,
                         ATTN_SMEM_BYTES);

    qkv_gemm_kernel<<<dim3(24, 64), 256>>>(x, wqkv);
    attn_kernel<<<dim3(32, 64), 256, ATTN_SMEM_BYTES>>>();
    out_gemm_kernel<<<dim3(8, 64), 256>>>(wout, out);
}

// round 3
// speedup vs baseline: 1.6767x; 1.6767x over previous
#include <cuda_runtime.h>
#include <cuda_bf16.h>
#include <cstdint>
#include <math.h>

// Problem constants
#define L_SEQ   2048
#define N_BATCH 4
#define EMB     1024
#define NH      16
#define DH      64
#define NHEADS  (N_BATCH * NH)      // 64
#define M_ROWS  (L_SEQ * N_BATCH)   // 8192

// ---------------------------------------------------------------------------
// Scratch (allocation-free: __device__ globals)
// ---------------------------------------------------------------------------
__device__ float g_q[(size_t)NHEADS * L_SEQ * DH];   // [head, l, d], pre-scaled
__device__ float g_k[(size_t)NHEADS * L_SEQ * DH];
__device__ float g_v[(size_t)NHEADS * L_SEQ * DH];

__device__ __nv_bfloat16 g_xhi[(size_t)M_ROWS * EMB];
__device__ __nv_bfloat16 g_xlo[(size_t)M_ROWS * EMB];
__device__ __nv_bfloat16 g_wqkvhi[(size_t)3 * EMB * EMB];
__device__ __nv_bfloat16 g_wqkvlo[(size_t)3 * EMB * EMB];
__device__ __nv_bfloat16 g_wouthi[(size_t)EMB * EMB];
__device__ __nv_bfloat16 g_woutlo[(size_t)EMB * EMB];
__device__ __nv_bfloat16 g_ctxhi[(size_t)M_ROWS * EMB];
__device__ __nv_bfloat16 g_ctxlo[(size_t)M_ROWS * EMB];

// ---------------------------------------------------------------------------
// PTX helpers (portable ISA only: cp.async / ldmatrix / mma.sync)
// ---------------------------------------------------------------------------
__device__ __forceinline__ uint32_t smem_u32(const void* p) {
    uint32_t a;
    asm("{ .reg .u64 t; cvta.to.shared.u64 t, %1; cvt.u32.u64 %0, t; }"
        : "=r"(a) : "l"(p));
    return a;
}

#define SWZ128(o) ((o) ^ (((o) >> 3) & 0x70))

#define CP_ASYNC16(dst, src) \
    asm volatile("cp.async.cg.shared.global [%0], [%1], 16;" \
                 :: "r"(dst), "l"(src) : "memory")
#define CP_ASYNC_COMMIT()  asm volatile("cp.async.commit_group;" ::: "memory")
#define CP_ASYNC_WAIT(n)   asm volatile("cp.async.wait_group %0;" :: "n"(n) : "memory")

#define LDSM_X4(r0, r1, r2, r3, addr) \
    asm volatile("ldmatrix.sync.aligned.m8n8.x4.shared.b16 {%0,%1,%2,%3}, [%4];" \
                 : "=r"(r0), "=r"(r1), "=r"(r2), "=r"(r3) : "r"(addr))

#define MMA_BF16(c, a, b0, b1) \
    asm volatile("mma.sync.aligned.m16n8k16.row.col.f32.bf16.bf16.f32 " \
                 "{%0,%1,%2,%3}, {%4,%5,%6,%7}, {%8,%9}, {%0,%1,%2,%3};" \
                 : "+f"((c)[0]), "+f"((c)[1]), "+f"((c)[2]), "+f"((c)[3]) \
                 : "r"((a)[0]), "r"((a)[1]), "r"((a)[2]), "r"((a)[3]), \
                   "r"(b0), "r"(b1))

// ---------------------------------------------------------------------------
// Kernel 0: fp32 -> (bf16 hi, bf16 lo) split
// ---------------------------------------------------------------------------
__global__ __launch_bounds__(256) void split_kernel(
    const float* __restrict__ src, __nv_bfloat16* __restrict__ hi,
    __nv_bfloat16* __restrict__ lo, int n)
{
    for (int i = blockIdx.x * blockDim.x + threadIdx.x; i < n;
         i += gridDim.x * blockDim.x) {
        float v = src[i];
        __nv_bfloat16 h = __float2bfloat16(v);
        hi[i] = h;
        lo[i] = __float2bfloat16(v - __bfloat162float(h));
    }
}

// ---------------------------------------------------------------------------
// HMMA GEMM: C[m, o] = sum_k A[m,k] * B[o,k]   (bf16 split, fp32 acc)
// CTA tile 128x128, K-chunk 64 bf16 (=128B SW128 rows), double-buffered
// cp.async, 8 warps in a 4(M) x 2(N) grid, warp tile 32x64.
// mode 0: QKV scatter epilogue (g_q scaled / g_k / g_v)
// mode 1: fp32 rows into `out`
// ---------------------------------------------------------------------------
#define TILE_B 16384                 // 128 rows x 128 B
#define STAGE_B (4 * TILE_B)         // Ahi, Alo, Bhi, Blo
#define GEMM_SMEM_BYTES (2 * STAGE_B) // 131072

__device__ __forceinline__ void gemm_load_stage(
    uint32_t smst, const __nv_bfloat16* const* srcs, const int* rowbase,
    int k0, int tid)
{
#pragma unroll
    for (int t = 0; t < 4; t++) {
#pragma unroll
        for (int r = 0; r < 4; r++) {
            const int q = r * 256 + tid;
            const int row = q >> 3;
            const int cc = q & 7;
            const uint32_t off = (uint32_t)(row * 128 + cc * 16);
            const __nv_bfloat16* src =
                srcs[t] + (size_t)(rowbase[t] + row) * EMB + k0 + cc * 8;
            CP_ASYNC16(smst + t * TILE_B + SWZ128(off), src);
        }
    }
    CP_ASYNC_COMMIT();
}

__global__ __launch_bounds__(256) void tc_gemm_kernel(
    const __nv_bfloat16* __restrict__ Ahi, const __nv_bfloat16* __restrict__ Alo,
    const __nv_bfloat16* __restrict__ Bhi, const __nv_bfloat16* __restrict__ Blo,
    float* __restrict__ out, int mode)
{
    extern __shared__ __align__(1024) char sm[];
    const uint32_t smb = smem_u32(sm);

    const int tid = threadIdx.x;
    const int wid = tid >> 5;
    const int lane = tid & 31;
    const int warp_m = wid & 3;          // 0..3  (32 rows each)
    const int warp_n = wid >> 2;         // 0..1  (64 cols each)
    const int bx = blockIdx.x;           // o tile
    const int by = blockIdx.y;           // m tile

    const __nv_bfloat16* srcs[4] = {Ahi, Alo, Bhi, Blo};
    const int rowbase[4] = {by * 128, by * 128, bx * 128, bx * 128};

    float c[2][8][4];
#pragma unroll
    for (int mt = 0; mt < 2; mt++)
#pragma unroll
        for (int nt = 0; nt < 8; nt++)
#pragma unroll
            for (int i = 0; i < 4; i++) c[mt][nt][i] = 0.0f;

    // ldmatrix per-lane logical offsets
    const int a_row = lane & 15;                      // row within 16
    const int a_cb  = (lane >> 4) * 16;               // 0 or 16 bytes
    const int b_row = (lane & 7) + ((lane >> 4) << 3);// n within 16
    const int b_cb  = ((lane >> 3) & 1) * 16;         // 0 or 16 bytes

    // prologue: load chunk 0 into stage 0
    gemm_load_stage(smb, srcs, rowbase, 0, tid);

    const int NCHUNK = EMB / 64;   // 16
    for (int ck = 0; ck < NCHUNK; ck++) {
        // prefetch next chunk into the other stage
        if (ck + 1 < NCHUNK)
            gemm_load_stage(smb + ((ck + 1) & 1) * STAGE_B, srcs, rowbase,
                            (ck + 1) * 64, tid);
        if (ck + 1 < NCHUNK) { CP_ASYNC_WAIT(1); } else { CP_ASYNC_WAIT(0); }
        __syncthreads();

        const uint32_t smAhi = smb + (ck & 1) * STAGE_B;
        const uint32_t smAlo = smAhi + TILE_B;
        const uint32_t smBhi = smAhi + 2 * TILE_B;
        const uint32_t smBlo = smAhi + 3 * TILE_B;

#pragma unroll
        for (int ks = 0; ks < 4; ks++) {
            const int kbyte = ks * 32;
            uint32_t ahi[2][4], alo[2][4];
#pragma unroll
            for (int mt = 0; mt < 2; mt++) {
                const uint32_t off =
                    (uint32_t)((warp_m * 32 + mt * 16 + a_row) * 128 + kbyte + a_cb);
                LDSM_X4(ahi[mt][0], ahi[mt][1], ahi[mt][2], ahi[mt][3],
                        smAhi + SWZ128(off));
                LDSM_X4(alo[mt][0], alo[mt][1], alo[mt][2], alo[mt][3],
                        smAlo + SWZ128(off));
            }
#pragma unroll
            for (int np = 0; np < 4; np++) {
                const uint32_t off =
                    (uint32_t)((warp_n * 64 + np * 16 + b_row) * 128 + kbyte + b_cb);
                uint32_t bh[4], bl[4];
                LDSM_X4(bh[0], bh[1], bh[2], bh[3], smBhi + SWZ128(off));
                LDSM_X4(bl[0], bl[1], bl[2], bl[3], smBlo + SWZ128(off));
#pragma unroll
                for (int mt = 0; mt < 2; mt++) {
                    float* c0 = c[mt][2 * np];
                    float* c1 = c[mt][2 * np + 1];
                    MMA_BF16(c0, ahi[mt], bh[0], bh[1]);
                    MMA_BF16(c0, alo[mt], bh[0], bh[1]);
                    MMA_BF16(c0, ahi[mt], bl[0], bl[1]);
                    MMA_BF16(c1, ahi[mt], bh[2], bh[3]);
                    MMA_BF16(c1, alo[mt], bh[2], bh[3]);
                    MMA_BF16(c1, ahi[mt], bl[2], bl[3]);
                }
            }
        }
        __syncthreads();   // stage consumed; safe to overwrite next iter
    }

    // ---- epilogue ----
    const int mrow_base = by * 128 + warp_m * 32 + (lane >> 2);
    const int ncol_base = warp_n * 64 + 2 * (lane & 3);
#pragma unroll
    for (int mt = 0; mt < 2; mt++) {
#pragma unroll
        for (int half = 0; half < 2; half++) {     // row, row+8
            const int m = mrow_base + mt * 16 + half * 8;
            if (mode == 0) {
                const int l = m >> 2;
                const int nb = m & 3;
                const int sec = bx >> 3;           // 0=q 1=k 2=v
#pragma unroll
                for (int nt = 0; nt < 8; nt++) {
                    const int o = bx * 128 + ncol_base + nt * 8;
                    const int h = (o & 1023) >> 6;
                    const int d = o & 63;
                    const size_t idx =
                        ((size_t)(nb * NH + h) * L_SEQ + l) * DH + d;
                    float2 v = make_float2(c[mt][nt][half * 2],
                                           c[mt][nt][half * 2 + 1]);
                    if (sec == 0) {
                        v.x *= 0.125f; v.y *= 0.125f;
                        *(float2*)(g_q + idx) = v;
                    } else if (sec == 1) {
                        *(float2*)(g_k + idx) = v;
                    } else {
                        *(float2*)(g_v + idx) = v;
                    }
                }
            } else {
                float* row = out + (size_t)m * EMB + bx * 128 + ncol_base;
#pragma unroll
                for (int nt = 0; nt < 8; nt++) {
                    float2 v = make_float2(c[mt][nt][half * 2],
                                           c[mt][nt][half * 2 + 1]);
                    *(float2*)(row + nt * 8) = v;
                }
            }
        }
    }
}

// ---------------------------------------------------------------------------
// Kernel 2: causal flash attention (fp32 SIMT). One CTA per (q-tile 64, head).
// Epilogue writes split-bf16 ctx for the HMMA out-projection.
// ---------------------------------------------------------------------------
#define LDT 65
#define LDV 68
#define ATTN_SMEM_FLOATS (3 * 64 * LDT + 64 * LDV)
#define ATTN_SMEM_BYTES  (ATTN_SMEM_FLOATS * 4)

__global__ __launch_bounds__(256) void attn_kernel()
{
    extern __shared__ float smf[];
    float* Qs = smf;
    float* Ks = Qs + 64 * LDT;
    float* Ps = Ks + 64 * LDT;
    float* Vs = Ps + 64 * LDT;

    const int qt   = blockIdx.x;
    const int head = blockIdx.y;
    const int qbase = qt * 64;
    const int tid = threadIdx.x;
    const int tx = tid & 15;
    const int ty = tid >> 4;

    const float* Qg = g_q + (size_t)head * L_SEQ * DH;
    const float* Kg = g_k + (size_t)head * L_SEQ * DH;
    const float* Vg = g_v + (size_t)head * L_SEQ * DH;

#pragma unroll
    for (int rep = 0; rep < 4; rep++) {
        const int idx = tid + rep * 256;
        const int r  = idx >> 4;
        const int d0 = (idx & 15) * 4;
        float4 q4 = *(const float4*)(Qg + (size_t)(qbase + r) * DH + d0);
        Qs[(d0 + 0) * LDT + r] = q4.x;
        Qs[(d0 + 1) * LDT + r] = q4.y;
        Qs[(d0 + 2) * LDT + r] = q4.z;
        Qs[(d0 + 3) * LDT + r] = q4.w;
    }

    float m_r[4], l_r[4], o_acc[4][4];
#pragma unroll
    for (int i = 0; i < 4; i++) {
        m_r[i] = -1e30f;
        l_r[i] = 0.0f;
#pragma unroll
        for (int j = 0; j < 4; j++) o_acc[i][j] = 0.0f;
    }

    for (int kt = 0; kt <= qt; kt++) {
        const int kbase = kt * 64;
        __syncthreads();
#pragma unroll
        for (int rep = 0; rep < 4; rep++) {
            const int idx = tid + rep * 256;
            const int cidx = idx >> 4;
            const int d0 = (idx & 15) * 4;
            float4 k4 = *(const float4*)(Kg + (size_t)(kbase + cidx) * DH + d0);
            Ks[(d0 + 0) * LDT + cidx] = k4.x;
            Ks[(d0 + 1) * LDT + cidx] = k4.y;
            Ks[(d0 + 2) * LDT + cidx] = k4.z;
            Ks[(d0 + 3) * LDT + cidx] = k4.w;
            float4 v4 = *(const float4*)(Vg + (size_t)(kbase + cidx) * DH + d0);
            *(float4*)(Vs + cidx * LDV + d0) = v4;
        }
        __syncthreads();

        float s[4][4];
#pragma unroll
        for (int i = 0; i < 4; i++)
#pragma unroll
            for (int j = 0; j < 4; j++) s[i][j] = 0.0f;
#pragma unroll
        for (int d = 0; d < 64; d++) {
            float a[4], b[4];
#pragma unroll
            for (int i = 0; i < 4; i++) a[i] = Qs[d * LDT + ty * 4 + i];
#pragma unroll
            for (int j = 0; j < 4; j++) b[j] = Ks[d * LDT + tx * 4 + j];
#pragma unroll
            for (int i = 0; i < 4; i++)
#pragma unroll
                for (int j = 0; j < 4; j++) s[i][j] += a[i] * b[j];
        }

        if (kt == qt) {
#pragma unroll
            for (int i = 0; i < 4; i++)
#pragma unroll
                for (int j = 0; j < 4; j++)
                    if (tx * 4 + j > ty * 4 + i) s[i][j] = -100000.0f;
        }

#pragma unroll
        for (int i = 0; i < 4; i++) {
            float mx = s[i][0];
#pragma unroll
            for (int j = 1; j < 4; j++) mx = fmaxf(mx, s[i][j]);
#pragma unroll
            for (int off = 8; off >= 1; off >>= 1)
                mx = fmaxf(mx, __shfl_xor_sync(0xffffffffu, mx, off));
            const float mn = fmaxf(m_r[i], mx);
            const float corr = __expf(m_r[i] - mn);
            m_r[i] = mn;
            l_r[i] *= corr;
#pragma unroll
            for (int j = 0; j < 4; j++) o_acc[i][j] *= corr;
            float rs = 0.0f;
#pragma unroll
            for (int j = 0; j < 4; j++) {
                const float p = __expf(s[i][j] - mn);
                s[i][j] = p;
                rs += p;
            }
#pragma unroll
            for (int off = 8; off >= 1; off >>= 1)
                rs += __shfl_xor_sync(0xffffffffu, rs, off);
            l_r[i] += rs;
        }

#pragma unroll
        for (int i = 0; i < 4; i++)
#pragma unroll
            for (int j = 0; j < 4; j++)
                Ps[(tx * 4 + j) * LDT + ty * 4 + i] = s[i][j];
        __syncthreads();

#pragma unroll
        for (int cc = 0; cc < 64; cc++) {
            float a[4], b[4];
#pragma unroll
            for (int i = 0; i < 4; i++) a[i] = Ps[cc * LDT + ty * 4 + i];
#pragma unroll
            for (int j = 0; j < 4; j++) b[j] = Vs[cc * LDV + tx * 4 + j];
#pragma unroll
            for (int i = 0; i < 4; i++)
#pragma unroll
                for (int j = 0; j < 4; j++) o_acc[i][j] += a[i] * b[j];
        }
    }

    // Normalize; write split-bf16 ctx in [L, N, E] layout
    const int n = head >> 4;
    const int h = head & 15;
#pragma unroll
    for (int i = 0; i < 4; i++) {
        const float inv = 1.0f / l_r[i];
        const int l = qbase + ty * 4 + i;
        const size_t base = ((size_t)l * N_BATCH + n) * EMB + h * DH + tx * 4;
        __nv_bfloat16 hi4[4], lo4[4];
#pragma unroll
        for (int j = 0; j < 4; j++) {
            float v = o_acc[i][j] * inv;
            __nv_bfloat16 hb = __float2bfloat16(v);
            hi4[j] = hb;
            lo4[j] = __float2bfloat16(v - __bfloat162float(hb));
        }
        *(uint2*)(g_ctxhi + base) = *(uint2*)hi4;
        *(uint2*)(g_ctxlo + base) = *(uint2*)lo4;
    }
}

// ---------------------------------------------------------------------------
extern "C" void kernel_launch(void* const* d_in, const int* in_sizes, int n_in,
                              void* d_out, int out_size)
{
    const float* x    = (const float*)d_in[0];   // [L, N, E]
    const float* wqkv = (const float*)d_in[1];   // [3E, E]
    const float* wout = (const float*)d_in[2];   // [E, E]
    float* out = (float*)d_out;                  // [L, N, E]

    cudaFuncSetAttribute(attn_kernel,
                         cudaFuncAttributeMaxDynamicSharedMemorySize,
                         ATTN_SMEM_BYTES);
    cudaFuncSetAttribute(tc_gemm_kernel,
                         cudaFuncAttributeMaxDynamicSharedMemorySize,
                         GEMM_SMEM_BYTES);

    __nv_bfloat16 *xhi, *xlo, *whi, *wlo, *ohi, *olo, *chi, *clo;
    cudaGetSymbolAddress((void**)&xhi, g_xhi);
    cudaGetSymbolAddress((void**)&xlo, g_xlo);
    cudaGetSymbolAddress((void**)&whi, g_wqkvhi);
    cudaGetSymbolAddress((void**)&wlo, g_wqkvlo);
    cudaGetSymbolAddress((void**)&ohi, g_wouthi);
    cudaGetSymbolAddress((void**)&olo, g_woutlo);
    cudaGetSymbolAddress((void**)&chi, g_ctxhi);
    cudaGetSymbolAddress((void**)&clo, g_ctxlo);

    split_kernel<<<1024, 256>>>(x, xhi, xlo, M_ROWS * EMB);
    split_kernel<<<1024, 256>>>(wqkv, whi, wlo, 3 * EMB * EMB);
    split_kernel<<<512, 256>>>(wout, ohi, olo, EMB * EMB);

    tc_gemm_kernel<<<dim3(24, 64), 256, GEMM_SMEM_BYTES>>>(
        xhi, xlo, whi, wlo, nullptr, 0);

    attn_kernel<<<dim3(32, 64), 256, ATTN_SMEM_BYTES>>>();

    tc_gemm_kernel<<<dim3(8, 64), 256, GEMM_SMEM_BYTES>>>(
        chi, clo, ohi, olo, out, 1);
}

// round 4
// speedup vs baseline: 3.0806x; 1.8373x over previous
#include <cuda_runtime.h>
#include <cuda_bf16.h>
#include <cstdint>
#include <math.h>

// Problem constants
#define L_SEQ   2048
#define N_BATCH 4
#define EMB     1024
#define NH      16
#define DH      64
#define NHEADS  (N_BATCH * NH)      // 64
#define M_ROWS  (L_SEQ * N_BATCH)   // 8192

// ---------------------------------------------------------------------------
// Scratch (allocation-free: __device__ globals)
// ---------------------------------------------------------------------------
__device__ __nv_bfloat16 g_qhi[(size_t)NHEADS * L_SEQ * DH];  // pre-scaled
__device__ __nv_bfloat16 g_qlo[(size_t)NHEADS * L_SEQ * DH];
__device__ __nv_bfloat16 g_khi[(size_t)NHEADS * L_SEQ * DH];
__device__ __nv_bfloat16 g_klo[(size_t)NHEADS * L_SEQ * DH];
__device__ __nv_bfloat16 g_vhi[(size_t)NHEADS * L_SEQ * DH];
__device__ __nv_bfloat16 g_vlo[(size_t)NHEADS * L_SEQ * DH];

__device__ __nv_bfloat16 g_xhi[(size_t)M_ROWS * EMB];
__device__ __nv_bfloat16 g_xlo[(size_t)M_ROWS * EMB];
__device__ __nv_bfloat16 g_wqkvhi[(size_t)3 * EMB * EMB];
__device__ __nv_bfloat16 g_wqkvlo[(size_t)3 * EMB * EMB];
__device__ __nv_bfloat16 g_wouthi[(size_t)EMB * EMB];
__device__ __nv_bfloat16 g_woutlo[(size_t)EMB * EMB];
__device__ __nv_bfloat16 g_ctxhi[(size_t)M_ROWS * EMB];
__device__ __nv_bfloat16 g_ctxlo[(size_t)M_ROWS * EMB];

// ---------------------------------------------------------------------------
// PTX helpers (portable ISA: cp.async / ldmatrix / mma.sync)
// ---------------------------------------------------------------------------
__device__ __forceinline__ uint32_t smem_u32(const void* p) {
    uint32_t a;
    asm("{ .reg .u64 t; cvta.to.shared.u64 t, %1; cvt.u32.u64 %0, t; }"
        : "=r"(a) : "l"(p));
    return a;
}

#define SWZ128(o) ((o) ^ (((o) >> 3) & 0x70))

#define CP_ASYNC16(dst, src) \
    asm volatile("cp.async.cg.shared.global [%0], [%1], 16;" \
                 :: "r"(dst), "l"(src) : "memory")
#define CP_ASYNC_COMMIT()  asm volatile("cp.async.commit_group;" ::: "memory")
#define CP_ASYNC_WAIT(n)   asm volatile("cp.async.wait_group %0;" :: "n"(n) : "memory")

#define LDSM_X4(r0, r1, r2, r3, addr) \
    asm volatile("ldmatrix.sync.aligned.m8n8.x4.shared.b16 {%0,%1,%2,%3}, [%4];" \
                 : "=r"(r0), "=r"(r1), "=r"(r2), "=r"(r3) : "r"(addr))

#define LDSM_X4T(r0, r1, r2, r3, addr) \
    asm volatile("ldmatrix.sync.aligned.m8n8.x4.trans.shared.b16 {%0,%1,%2,%3}, [%4];" \
                 : "=r"(r0), "=r"(r1), "=r"(r2), "=r"(r3) : "r"(addr))

#define MMA_BF16(c, a, b0, b1) \
    asm volatile("mma.sync.aligned.m16n8k16.row.col.f32.bf16.bf16.f32 " \
                 "{%0,%1,%2,%3}, {%4,%5,%6,%7}, {%8,%9}, {%0,%1,%2,%3};" \
                 : "+f"((c)[0]), "+f"((c)[1]), "+f"((c)[2]), "+f"((c)[3]) \
                 : "r"((a)[0]), "r"((a)[1]), "r"((a)[2]), "r"((a)[3]), \
                   "r"(b0), "r"(b1))

// pack two fp32 into bf16x2 hi and residual-lo bf16x2
__device__ __forceinline__ void pack_hilo(float f0, float f1,
                                          uint32_t& hi, uint32_t& lo) {
    __nv_bfloat162 h = __floats2bfloat162_rn(f0, f1);   // x=f0 (low), y=f1
    hi = *reinterpret_cast<uint32_t*>(&h);
    float g0 = __bfloat162float(h.x);
    float g1 = __bfloat162float(h.y);
    __nv_bfloat162 l2 = __floats2bfloat162_rn(f0 - g0, f1 - g1);
    lo = *reinterpret_cast<uint32_t*>(&l2);
}

// ---------------------------------------------------------------------------
// Kernel 0: fp32 -> (bf16 hi, bf16 lo) split
// ---------------------------------------------------------------------------
__global__ __launch_bounds__(256) void split_kernel(
    const float* __restrict__ src, __nv_bfloat16* __restrict__ hi,
    __nv_bfloat16* __restrict__ lo, int n)
{
    for (int i = blockIdx.x * blockDim.x + threadIdx.x; i < n;
         i += gridDim.x * blockDim.x) {
        float v = src[i];
        __nv_bfloat16 h = __float2bfloat16(v);
        hi[i] = h;
        lo[i] = __float2bfloat16(v - __bfloat162float(h));
    }
}

// ---------------------------------------------------------------------------
// HMMA GEMM: C[m, o] = sum_k A[m,k] * B[o,k]   (bf16 split, fp32 acc)
// CTA 128x128, K-chunk 64 bf16 (128B SW128 rows), double-buffered cp.async,
// 8 warps 4(M)x2(N), warp tile 32x64.
// mode 0: QKV scatter epilogue -> bf16 hi/lo q(scaled)/k/v [head][l][d]
// mode 1: fp32 rows into `out`
// ---------------------------------------------------------------------------
#define TILE_B 16384
#define STAGE_B (4 * TILE_B)
#define GEMM_SMEM_BYTES (2 * STAGE_B)

__device__ __forceinline__ void gemm_load_stage(
    uint32_t smst, const __nv_bfloat16* const* srcs, const int* rowbase,
    int k0, int tid)
{
#pragma unroll
    for (int t = 0; t < 4; t++) {
#pragma unroll
        for (int r = 0; r < 4; r++) {
            const int q = r * 256 + tid;
            const int row = q >> 3;
            const int cc = q & 7;
            const uint32_t off = (uint32_t)(row * 128 + cc * 16);
            const __nv_bfloat16* src =
                srcs[t] + (size_t)(rowbase[t] + row) * EMB + k0 + cc * 8;
            CP_ASYNC16(smst + t * TILE_B + SWZ128(off), src);
        }
    }
    CP_ASYNC_COMMIT();
}

__global__ __launch_bounds__(256) void tc_gemm_kernel(
    const __nv_bfloat16* __restrict__ Ahi, const __nv_bfloat16* __restrict__ Alo,
    const __nv_bfloat16* __restrict__ Bhi, const __nv_bfloat16* __restrict__ Blo,
    float* __restrict__ out, int mode)
{
    extern __shared__ __align__(1024) char sm[];
    const uint32_t smb = smem_u32(sm);

    const int tid = threadIdx.x;
    const int wid = tid >> 5;
    const int lane = tid & 31;
    const int warp_m = wid & 3;
    const int warp_n = wid >> 2;
    const int bx = blockIdx.x;
    const int by = blockIdx.y;

    const __nv_bfloat16* srcs[4] = {Ahi, Alo, Bhi, Blo};
    const int rowbase[4] = {by * 128, by * 128, bx * 128, bx * 128};

    float c[2][8][4];
#pragma unroll
    for (int mt = 0; mt < 2; mt++)
#pragma unroll
        for (int nt = 0; nt < 8; nt++)
#pragma unroll
            for (int i = 0; i < 4; i++) c[mt][nt][i] = 0.0f;

    const int a_row = lane & 15;
    const int a_cb  = (lane >> 4) * 16;
    const int b_row = (lane & 7) + ((lane >> 4) << 3);
    const int b_cb  = ((lane >> 3) & 1) * 16;

    gemm_load_stage(smb, srcs, rowbase, 0, tid);

    const int NCHUNK = EMB / 64;
    for (int ck = 0; ck < NCHUNK; ck++) {
        if (ck + 1 < NCHUNK)
            gemm_load_stage(smb + ((ck + 1) & 1) * STAGE_B, srcs, rowbase,
                            (ck + 1) * 64, tid);
        if (ck + 1 < NCHUNK) { CP_ASYNC_WAIT(1); } else { CP_ASYNC_WAIT(0); }
        __syncthreads();

        const uint32_t smAhi = smb + (ck & 1) * STAGE_B;
        const uint32_t smAlo = smAhi + TILE_B;
        const uint32_t smBhi = smAhi + 2 * TILE_B;
        const uint32_t smBlo = smAhi + 3 * TILE_B;

#pragma unroll
        for (int ks = 0; ks < 4; ks++) {
            const int kbyte = ks * 32;
            uint32_t ahi[2][4], alo[2][4];
#pragma unroll
            for (int mt = 0; mt < 2; mt++) {
                const uint32_t off =
                    (uint32_t)((warp_m * 32 + mt * 16 + a_row) * 128 + kbyte + a_cb);
                LDSM_X4(ahi[mt][0], ahi[mt][1], ahi[mt][2], ahi[mt][3],
                        smAhi + SWZ128(off));
                LDSM_X4(alo[mt][0], alo[mt][1], alo[mt][2], alo[mt][3],
                        smAlo + SWZ128(off));
            }
#pragma unroll
            for (int np = 0; np < 4; np++) {
                const uint32_t off =
                    (uint32_t)((warp_n * 64 + np * 16 + b_row) * 128 + kbyte + b_cb);
                uint32_t bh[4], bl[4];
                LDSM_X4(bh[0], bh[1], bh[2], bh[3], smBhi + SWZ128(off));
                LDSM_X4(bl[0], bl[1], bl[2], bl[3], smBlo + SWZ128(off));
#pragma unroll
                for (int mt = 0; mt < 2; mt++) {
                    float* c0 = c[mt][2 * np];
                    float* c1 = c[mt][2 * np + 1];
                    MMA_BF16(c0, ahi[mt], bh[0], bh[1]);
                    MMA_BF16(c0, alo[mt], bh[0], bh[1]);
                    MMA_BF16(c0, ahi[mt], bl[0], bl[1]);
                    MMA_BF16(c1, ahi[mt], bh[2], bh[3]);
                    MMA_BF16(c1, alo[mt], bh[2], bh[3]);
                    MMA_BF16(c1, ahi[mt], bl[2], bl[3]);
                }
            }
        }
        __syncthreads();
    }

    // ---- epilogue ----
    const int mrow_base = by * 128 + warp_m * 32 + (lane >> 2);
    const int ncol_base = warp_n * 64 + 2 * (lane & 3);
#pragma unroll
    for (int mt = 0; mt < 2; mt++) {
#pragma unroll
        for (int half = 0; half < 2; half++) {
            const int m = mrow_base + mt * 16 + half * 8;
            if (mode == 0) {
                const int l = m >> 2;
                const int nb = m & 3;
                const int sec = bx >> 3;      // 0=q 1=k 2=v
#pragma unroll
                for (int nt = 0; nt < 8; nt++) {
                    const int o = bx * 128 + ncol_base + nt * 8;
                    const int h = (o & 1023) >> 6;
                    const int d = o & 63;
                    const size_t idx =
                        ((size_t)(nb * NH + h) * L_SEQ + l) * DH + d;
                    float v0 = c[mt][nt][half * 2];
                    float v1 = c[mt][nt][half * 2 + 1];
                    if (sec == 0) { v0 *= 0.125f; v1 *= 0.125f; }
                    uint32_t hi, lo;
                    pack_hilo(v0, v1, hi, lo);
                    if (sec == 0) {
                        *(uint32_t*)(g_qhi + idx) = hi;
                        *(uint32_t*)(g_qlo + idx) = lo;
                    } else if (sec == 1) {
                        *(uint32_t*)(g_khi + idx) = hi;
                        *(uint32_t*)(g_klo + idx) = lo;
                    } else {
                        *(uint32_t*)(g_vhi + idx) = hi;
                        *(uint32_t*)(g_vlo + idx) = lo;
                    }
                }
            } else {
                float* row = out + (size_t)m * EMB + bx * 128 + ncol_base;
#pragma unroll
                for (int nt = 0; nt < 8; nt++) {
                    float2 v = make_float2(c[mt][nt][half * 2],
                                           c[mt][nt][half * 2 + 1]);
                    *(float2*)(row + nt * 8) = v;
                }
            }
        }
    }
}

// ---------------------------------------------------------------------------
// Kernel 2: causal flash attention on HMMA (bf16 split, fp32 softmax).
// CTA = (head, 128 q rows), 8 warps x 16 rows, 64-key tiles double-buffered.
// ---------------------------------------------------------------------------
#define AT_TILE 8192                  // 64 rows x 128 B
#define AT_STAGE (4 * AT_TILE)        // Khi, Klo, Vhi, Vlo
#define ATTN_SMEM_BYTES (2 * AT_STAGE)

__device__ __forceinline__ void attn_load_stage(
    uint32_t smst,
    const __nv_bfloat16* Khi, const __nv_bfloat16* Klo,
    const __nv_bfloat16* Vhi, const __nv_bfloat16* Vlo,
    int kbase, int tid)
{
    const __nv_bfloat16* srcs[4] = {Khi, Klo, Vhi, Vlo};
#pragma unroll
    for (int t = 0; t < 4; t++) {
#pragma unroll
        for (int it = 0; it < 2; it++) {
            const int idx = it * 256 + tid;       // 0..511
            const int row = idx >> 3;
            const int cc = idx & 7;
            const uint32_t off = (uint32_t)(row * 128 + cc * 16);
            CP_ASYNC16(smst + t * AT_TILE + SWZ128(off),
                       srcs[t] + (size_t)(kbase + row) * DH + cc * 8);
        }
    }
    CP_ASYNC_COMMIT();
}

__global__ __launch_bounds__(256) void attn_hmma_kernel()
{
    extern __shared__ __align__(1024) char sm[];
    const uint32_t smb = smem_u32(sm);

    const int tid = threadIdx.x;
    const int wid = tid >> 5;
    const int lane = tid & 31;
    const int bqt = blockIdx.x;           // 0..15
    const int head = blockIdx.y;          // 0..63
    const int qbase = bqt * 128;

    const size_t hoff = (size_t)head * L_SEQ * DH;
    const __nv_bfloat16* Qhi = g_qhi + hoff;
    const __nv_bfloat16* Qlo = g_qlo + hoff;
    const __nv_bfloat16* Khi = g_khi + hoff;
    const __nv_bfloat16* Klo = g_klo + hoff;
    const __nv_bfloat16* Vhi = g_vhi + hoff;
    const __nv_bfloat16* Vlo = g_vlo + hoff;

    // Q fragments (direct LDG, once per CTA)
    const int r0 = qbase + wid * 16 + (lane >> 2);
    uint32_t qh[4][4], ql[4][4];
#pragma unroll
    for (int kc = 0; kc < 4; kc++) {
        const int d0 = kc * 16 + 2 * (lane & 3);
        qh[kc][0] = *(const uint32_t*)(Qhi + (size_t)r0 * DH + d0);
        qh[kc][1] = *(const uint32_t*)(Qhi + (size_t)(r0 + 8) * DH + d0);
        qh[kc][2] = *(const uint32_t*)(Qhi + (size_t)r0 * DH + d0 + 8);
        qh[kc][3] = *(const uint32_t*)(Qhi + (size_t)(r0 + 8) * DH + d0 + 8);
        ql[kc][0] = *(const uint32_t*)(Qlo + (size_t)r0 * DH + d0);
        ql[kc][1] = *(const uint32_t*)(Qlo + (size_t)(r0 + 8) * DH + d0);
        ql[kc][2] = *(const uint32_t*)(Qlo + (size_t)r0 * DH + d0 + 8);
        ql[kc][3] = *(const uint32_t*)(Qlo + (size_t)(r0 + 8) * DH + d0 + 8);
    }

    float o[8][4];
#pragma unroll
    for (int t = 0; t < 8; t++)
#pragma unroll
        for (int i = 0; i < 4; i++) o[t][i] = 0.0f;
    float m0 = -1e30f, m1 = -1e30f, l0 = 0.0f, l1 = 0.0f;

    const int b_row = (lane & 7) + ((lane >> 4) << 3);
    const int b_cb  = ((lane >> 3) & 1) * 16;
    const int v_row = ((lane >> 3) & 1) * 8 + (lane & 7);
    const int v_cb  = ((lane >> 4) & 1) * 16;

    const int nkt = qbase / 64 + 2;
    attn_load_stage(smb, Khi, Klo, Vhi, Vlo, 0, tid);

    for (int kt = 0; kt < nkt; kt++) {
        if (kt + 1 < nkt)
            attn_load_stage(smb + ((kt + 1) & 1) * AT_STAGE,
                            Khi, Klo, Vhi, Vlo, (kt + 1) * 64, tid);
        if (kt + 1 < nkt) { CP_ASYNC_WAIT(1); } else { CP_ASYNC_WAIT(0); }
        __syncthreads();

        const uint32_t sKh = smb + (kt & 1) * AT_STAGE;
        const uint32_t sKl = sKh + AT_TILE;
        const uint32_t sVh = sKh + 2 * AT_TILE;
        const uint32_t sVl = sKh + 3 * AT_TILE;

        // ---- S = Q K^T (3-pass split) ----
        float c[8][4];
#pragma unroll
        for (int t = 0; t < 8; t++)
#pragma unroll
            for (int i = 0; i < 4; i++) c[t][i] = 0.0f;

#pragma unroll
        for (int ng = 0; ng < 4; ng++) {
#pragma unroll
            for (int kc = 0; kc < 4; kc++) {
                const uint32_t off =
                    (uint32_t)((ng * 16 + b_row) * 128 + kc * 32 + b_cb);
                uint32_t bh[4], bl[4];
                LDSM_X4(bh[0], bh[1], bh[2], bh[3], sKh + SWZ128(off));
                LDSM_X4(bl[0], bl[1], bl[2], bl[3], sKl + SWZ128(off));
                MMA_BF16(c[2 * ng],     qh[kc], bh[0], bh[1]);
                MMA_BF16(c[2 * ng],     ql[kc], bh[0], bh[1]);
                MMA_BF16(c[2 * ng],     qh[kc], bl[0], bl[1]);
                MMA_BF16(c[2 * ng + 1], qh[kc], bh[2], bh[3]);
                MMA_BF16(c[2 * ng + 1], ql[kc], bh[2], bh[3]);
                MMA_BF16(c[2 * ng + 1], qh[kc], bl[2], bl[3]);
            }
        }

        // ---- causal mask (boundary tiles only) ----
        const int kb = kt * 64;
        if (kb + 63 > r0) {
#pragma unroll
            for (int t = 0; t < 8; t++) {
                const int col = kb + t * 8 + 2 * (lane & 3);
                if (col > r0)         c[t][0] = -1e30f;
                if (col + 1 > r0)     c[t][1] = -1e30f;
                if (col > r0 + 8)     c[t][2] = -1e30f;
                if (col + 1 > r0 + 8) c[t][3] = -1e30f;
            }
        }

        // ---- online softmax ----
        float mx0 = -1e30f, mx1 = -1e30f;
#pragma unroll
        for (int t = 0; t < 8; t++) {
            mx0 = fmaxf(mx0, fmaxf(c[t][0], c[t][1]));
            mx1 = fmaxf(mx1, fmaxf(c[t][2], c[t][3]));
        }
        mx0 = fmaxf(mx0, __shfl_xor_sync(0xffffffffu, mx0, 1));
        mx0 = fmaxf(mx0, __shfl_xor_sync(0xffffffffu, mx0, 2));
        mx1 = fmaxf(mx1, __shfl_xor_sync(0xffffffffu, mx1, 1));
        mx1 = fmaxf(mx1, __shfl_xor_sync(0xffffffffu, mx1, 2));

        const float mn0 = fmaxf(m0, mx0);
        const float mn1 = fmaxf(m1, mx1);
        const float corr0 = __expf(m0 - mn0);
        const float corr1 = __expf(m1 - mn1);
        m0 = mn0; m1 = mn1;

        float rs0 = 0.0f, rs1 = 0.0f;
#pragma unroll
        for (int t = 0; t < 8; t++) {
            c[t][0] = __expf(c[t][0] - mn0); rs0 += c[t][0];
            c[t][1] = __expf(c[t][1] - mn0); rs0 += c[t][1];
            c[t][2] = __expf(c[t][2] - mn1); rs1 += c[t][2];
            c[t][3] = __expf(c[t][3] - mn1); rs1 += c[t][3];
        }
        rs0 += __shfl_xor_sync(0xffffffffu, rs0, 1);
        rs0 += __shfl_xor_sync(0xffffffffu, rs0, 2);
        rs1 += __shfl_xor_sync(0xffffffffu, rs1, 1);
        rs1 += __shfl_xor_sync(0xffffffffu, rs1, 2);
        l0 = l0 * corr0 + rs0;
        l1 = l1 * corr1 + rs1;

#pragma unroll
        for (int t = 0; t < 8; t++) {
            o[t][0] *= corr0; o[t][1] *= corr0;
            o[t][2] *= corr1; o[t][3] *= corr1;
        }

        // ---- O += P V (3-pass split), P re-packed in-register ----
#pragma unroll
        for (int kc = 0; kc < 4; kc++) {
            uint32_t ah[4], al[4];
            pack_hilo(c[2 * kc][0],     c[2 * kc][1],     ah[0], al[0]);
            pack_hilo(c[2 * kc][2],     c[2 * kc][3],     ah[1], al[1]);
            pack_hilo(c[2 * kc + 1][0], c[2 * kc + 1][1], ah[2], al[2]);
            pack_hilo(c[2 * kc + 1][2], c[2 * kc + 1][3], ah[3], al[3]);
#pragma unroll
            for (int ng = 0; ng < 4; ng++) {
                const uint32_t off =
                    (uint32_t)((kc * 16 + v_row) * 128 + ng * 32 + v_cb);
                uint32_t vh[4], vl[4];
                LDSM_X4T(vh[0], vh[1], vh[2], vh[3], sVh + SWZ128(off));
                LDSM_X4T(vl[0], vl[1], vl[2], vl[3], sVl + SWZ128(off));
                MMA_BF16(o[2 * ng],     ah, vh[0], vh[1]);
                MMA_BF16(o[2 * ng],     al, vh[0], vh[1]);
                MMA_BF16(o[2 * ng],     ah, vl[0], vl[1]);
                MMA_BF16(o[2 * ng + 1], ah, vh[2], vh[3]);
                MMA_BF16(o[2 * ng + 1], al, vh[2], vh[3]);
                MMA_BF16(o[2 * ng + 1], ah, vl[2], vl[3]);
            }
        }
        __syncthreads();
    }

    // ---- epilogue: normalize, split to bf16 ctx [L][N][E] ----
    const float inv0 = 1.0f / l0;
    const float inv1 = 1.0f / l1;
    const int nb = head >> 4;
    const int hh = head & 15;
    const size_t base0 =
        ((size_t)r0 * N_BATCH + nb) * EMB + hh * DH + 2 * (lane & 3);
    const size_t base1 = base0 + (size_t)8 * N_BATCH * EMB;
#pragma unroll
    for (int t = 0; t < 8; t++) {
        uint32_t hi, lo;
        pack_hilo(o[t][0] * inv0, o[t][1] * inv0, hi, lo);
        *(uint32_t*)(g_ctxhi + base0 + t * 8) = hi;
        *(uint32_t*)(g_ctxlo + base0 + t * 8) = lo;
        pack_hilo(o[t][2] * inv1, o[t][3] * inv1, hi, lo);
        *(uint32_t*)(g_ctxhi + base1 + t * 8) = hi;
        *(uint32_t*)(g_ctxlo + base1 + t * 8) = lo;
    }
}

// ---------------------------------------------------------------------------
extern "C" void kernel_launch(void* const* d_in, const int* in_sizes, int n_in,
                              void* d_out, int out_size)
{
    const float* x    = (const float*)d_in[0];   // [L, N, E]
    const float* wqkv = (const float*)d_in[1];   // [3E, E]
    const float* wout = (const float*)d_in[2];   // [E, E]
    float* out = (float*)d_out;                  // [L, N, E]

    cudaFuncSetAttribute(tc_gemm_kernel,
                         cudaFuncAttributeMaxDynamicSharedMemorySize,
                         GEMM_SMEM_BYTES);
    cudaFuncSetAttribute(attn_hmma_kernel,
                         cudaFuncAttributeMaxDynamicSharedMemorySize,
                         ATTN_SMEM_BYTES);

    __nv_bfloat16 *xhi, *xlo, *whi, *wlo, *ohi, *olo, *chi, *clo;
    cudaGetSymbolAddress((void**)&xhi, g_xhi);
    cudaGetSymbolAddress((void**)&xlo, g_xlo);
    cudaGetSymbolAddress((void**)&whi, g_wqkvhi);
    cudaGetSymbolAddress((void**)&wlo, g_wqkvlo);
    cudaGetSymbolAddress((void**)&ohi, g_wouthi);
    cudaGetSymbolAddress((void**)&olo, g_woutlo);
    cudaGetSymbolAddress((void**)&chi, g_ctxhi);
    cudaGetSymbolAddress((void**)&clo, g_ctxlo);

    split_kernel<<<1024, 256>>>(x, xhi, xlo, M_ROWS * EMB);
    split_kernel<<<1024, 256>>>(wqkv, whi, wlo, 3 * EMB * EMB);
    split_kernel<<<512, 256>>>(wout, ohi, olo, EMB * EMB);

    tc_gemm_kernel<<<dim3(24, 64), 256, GEMM_SMEM_BYTES>>>(
        xhi, xlo, whi, wlo, nullptr, 0);

    attn_hmma_kernel<<<dim3(16, 64), 256, ATTN_SMEM_BYTES>>>();

    tc_gemm_kernel<<<dim3(8, 64), 256, GEMM_SMEM_BYTES>>>(
        chi, clo, ohi, olo, out, 1);
}

// round 5
// speedup vs baseline: 3.2134x; 1.0431x over previous
#include <cuda_runtime.h>
#include <cuda_bf16.h>
#include <cstdint>
#include <math.h>

// Problem constants
#define L_SEQ   2048
#define N_BATCH 4
#define EMB     1024
#define NH      16
#define DH      64
#define NHEADS  (N_BATCH * NH)      // 64
#define M_ROWS  (L_SEQ * N_BATCH)   // 8192

// ---------------------------------------------------------------------------
// Scratch (allocation-free: __device__ globals)
// ---------------------------------------------------------------------------
__device__ __nv_bfloat16 g_qhi[(size_t)NHEADS * L_SEQ * DH];  // pre-scaled
__device__ __nv_bfloat16 g_qlo[(size_t)NHEADS * L_SEQ * DH];
__device__ __nv_bfloat16 g_khi[(size_t)NHEADS * L_SEQ * DH];
__device__ __nv_bfloat16 g_klo[(size_t)NHEADS * L_SEQ * DH];
__device__ __nv_bfloat16 g_vhi[(size_t)NHEADS * L_SEQ * DH];
__device__ __nv_bfloat16 g_vlo[(size_t)NHEADS * L_SEQ * DH];

__device__ __nv_bfloat16 g_xhi[(size_t)M_ROWS * EMB];
__device__ __nv_bfloat16 g_xlo[(size_t)M_ROWS * EMB];
__device__ __nv_bfloat16 g_wqkvhi[(size_t)3 * EMB * EMB];
__device__ __nv_bfloat16 g_wqkvlo[(size_t)3 * EMB * EMB];
__device__ __nv_bfloat16 g_wouthi[(size_t)EMB * EMB];
__device__ __nv_bfloat16 g_woutlo[(size_t)EMB * EMB];
__device__ __nv_bfloat16 g_ctxhi[(size_t)M_ROWS * EMB];
__device__ __nv_bfloat16 g_ctxlo[(size_t)M_ROWS * EMB];

// ---------------------------------------------------------------------------
// PTX helpers (portable ISA: cp.async / ldmatrix / mma.sync)
// ---------------------------------------------------------------------------
__device__ __forceinline__ uint32_t smem_u32(const void* p) {
    uint32_t a;
    asm("{ .reg .u64 t; cvta.to.shared.u64 t, %1; cvt.u32.u64 %0, t; }"
        : "=r"(a) : "l"(p));
    return a;
}

#define SWZ128(o) ((o) ^ (((o) >> 3) & 0x70))

#define CP_ASYNC16(dst, src) \
    asm volatile("cp.async.cg.shared.global [%0], [%1], 16;" \
                 :: "r"(dst), "l"(src) : "memory")
#define CP_ASYNC_COMMIT()  asm volatile("cp.async.commit_group;" ::: "memory")
#define CP_ASYNC_WAIT(n)   asm volatile("cp.async.wait_group %0;" :: "n"(n) : "memory")

#define LDSM_X4(r0, r1, r2, r3, addr) \
    asm volatile("ldmatrix.sync.aligned.m8n8.x4.shared.b16 {%0,%1,%2,%3}, [%4];" \
                 : "=r"(r0), "=r"(r1), "=r"(r2), "=r"(r3) : "r"(addr))

#define LDSM_X4T(r0, r1, r2, r3, addr) \
    asm volatile("ldmatrix.sync.aligned.m8n8.x4.trans.shared.b16 {%0,%1,%2,%3}, [%4];" \
                 : "=r"(r0), "=r"(r1), "=r"(r2), "=r"(r3) : "r"(addr))

#define MMA_BF16(c, a, b0, b1) \
    asm volatile("mma.sync.aligned.m16n8k16.row.col.f32.bf16.bf16.f32 " \
                 "{%0,%1,%2,%3}, {%4,%5,%6,%7}, {%8,%9}, {%0,%1,%2,%3};" \
                 : "+f"((c)[0]), "+f"((c)[1]), "+f"((c)[2]), "+f"((c)[3]) \
                 : "r"((a)[0]), "r"((a)[1]), "r"((a)[2]), "r"((a)[3]), \
                   "r"(b0), "r"(b1))

// pack two fp32 into bf16x2 hi and residual-lo bf16x2
__device__ __forceinline__ void pack_hilo(float f0, float f1,
                                          uint32_t& hi, uint32_t& lo) {
    __nv_bfloat162 h = __floats2bfloat162_rn(f0, f1);
    hi = *reinterpret_cast<uint32_t*>(&h);
    float g0 = __bfloat162float(h.x);
    float g1 = __bfloat162float(h.y);
    __nv_bfloat162 l2 = __floats2bfloat162_rn(f0 - g0, f1 - g1);
    lo = *reinterpret_cast<uint32_t*>(&l2);
}

// ---------------------------------------------------------------------------
// Kernel 0: fp32 -> (bf16 hi, bf16 lo) split
// ---------------------------------------------------------------------------
__global__ __launch_bounds__(256) void split_kernel(
    const float* __restrict__ src, __nv_bfloat16* __restrict__ hi,
    __nv_bfloat16* __restrict__ lo, int n)
{
    for (int i = blockIdx.x * blockDim.x + threadIdx.x; i < n;
         i += gridDim.x * blockDim.x) {
        float v = src[i];
        __nv_bfloat16 h = __float2bfloat16(v);
        hi[i] = h;
        lo[i] = __float2bfloat16(v - __bfloat162float(h));
    }
}

// ---------------------------------------------------------------------------
// HMMA GEMM: C[m, o] = sum_k A[m,k] * B[o,k]   (bf16 split, fp32 acc)
// CTA 128x256, K-chunk 64 bf16 (128B SW128 rows), double-buffered cp.async,
// 8 warps 2(M)x4(N), warp tile 64x64.
// mode 0: QKV scatter epilogue -> bf16 hi/lo q(scaled)/k/v [head][l][d]
// mode 1: fp32 rows into `out`
// ---------------------------------------------------------------------------
#define A_TILE_B 16384                // 128 rows x 128 B
#define B_TILE_B 32768                // 256 rows x 128 B
#define STAGE_B (2 * A_TILE_B + 2 * B_TILE_B)   // 96 KB
#define GEMM_SMEM_BYTES (2 * STAGE_B)           // 192 KB
#define SM_A_HI 0
#define SM_A_LO A_TILE_B
#define SM_B_HI (2 * A_TILE_B)
#define SM_B_LO (2 * A_TILE_B + B_TILE_B)

__device__ __forceinline__ void gemm_load_stage(
    uint32_t smst,
    const __nv_bfloat16* Ahi, const __nv_bfloat16* Alo,
    const __nv_bfloat16* Bhi, const __nv_bfloat16* Blo,
    int arow0, int brow0, int k0, int tid)
{
    // A tiles: 128 rows x 8 16B-chunks = 1024 chunks each
#pragma unroll
    for (int r = 0; r < 4; r++) {
        const int idx = r * 256 + tid;
        const int row = idx >> 3;
        const int cc = idx & 7;
        const uint32_t off = SWZ128((uint32_t)(row * 128 + cc * 16));
        CP_ASYNC16(smst + SM_A_HI + off,
                   Ahi + (size_t)(arow0 + row) * EMB + k0 + cc * 8);
        CP_ASYNC16(smst + SM_A_LO + off,
                   Alo + (size_t)(arow0 + row) * EMB + k0 + cc * 8);
    }
    // B tiles: 256 rows x 8 chunks = 2048 chunks each
#pragma unroll
    for (int r = 0; r < 8; r++) {
        const int idx = r * 256 + tid;
        const int row = idx >> 3;
        const int cc = idx & 7;
        const uint32_t off = SWZ128((uint32_t)(row * 128 + cc * 16));
        CP_ASYNC16(smst + SM_B_HI + off,
                   Bhi + (size_t)(brow0 + row) * EMB + k0 + cc * 8);
        CP_ASYNC16(smst + SM_B_LO + off,
                   Blo + (size_t)(brow0 + row) * EMB + k0 + cc * 8);
    }
    CP_ASYNC_COMMIT();
}

__global__ __launch_bounds__(256) void tc_gemm_kernel(
    const __nv_bfloat16* __restrict__ Ahi, const __nv_bfloat16* __restrict__ Alo,
    const __nv_bfloat16* __restrict__ Bhi, const __nv_bfloat16* __restrict__ Blo,
    float* __restrict__ out, int mode)
{
    extern __shared__ __align__(1024) char sm[];
    const uint32_t smb = smem_u32(sm);

    const int tid = threadIdx.x;
    const int wid = tid >> 5;
    const int lane = tid & 31;
    const int warp_m = wid & 1;          // 0..1 (64 rows each)
    const int warp_n = wid >> 1;         // 0..3 (64 cols each)
    const int bx = blockIdx.x;           // o tile (256 wide)
    const int by = blockIdx.y;           // m tile (128 tall)

    float c[4][8][4];
#pragma unroll
    for (int mt = 0; mt < 4; mt++)
#pragma unroll
        for (int nt = 0; nt < 8; nt++)
#pragma unroll
            for (int i = 0; i < 4; i++) c[mt][nt][i] = 0.0f;

    const int a_row = lane & 15;
    const int a_cb  = (lane >> 4) * 16;
    const int b_row = (lane & 7) + ((lane >> 4) << 3);
    const int b_cb  = ((lane >> 3) & 1) * 16;

    gemm_load_stage(smb, Ahi, Alo, Bhi, Blo, by * 128, bx * 256, 0, tid);

    const int NCHUNK = EMB / 64;   // 16
    for (int ck = 0; ck < NCHUNK; ck++) {
        if (ck + 1 < NCHUNK)
            gemm_load_stage(smb + ((ck + 1) & 1) * STAGE_B, Ahi, Alo, Bhi, Blo,
                            by * 128, bx * 256, (ck + 1) * 64, tid);
        if (ck + 1 < NCHUNK) { CP_ASYNC_WAIT(1); } else { CP_ASYNC_WAIT(0); }
        __syncthreads();

        const uint32_t st = smb + (ck & 1) * STAGE_B;
        const uint32_t smAhi = st + SM_A_HI;
        const uint32_t smAlo = st + SM_A_LO;
        const uint32_t smBhi = st + SM_B_HI;
        const uint32_t smBlo = st + SM_B_LO;

#pragma unroll
        for (int ks = 0; ks < 4; ks++) {
            const int kbyte = ks * 32;
            uint32_t ahi[4][4], alo[4][4];
#pragma unroll
            for (int mt = 0; mt < 4; mt++) {
                const uint32_t off = SWZ128(
                    (uint32_t)((warp_m * 64 + mt * 16 + a_row) * 128 + kbyte + a_cb));
                LDSM_X4(ahi[mt][0], ahi[mt][1], ahi[mt][2], ahi[mt][3],
                        smAhi + off);
                LDSM_X4(alo[mt][0], alo[mt][1], alo[mt][2], alo[mt][3],
                        smAlo + off);
            }
#pragma unroll
            for (int np = 0; np < 4; np++) {
                const uint32_t off = SWZ128(
                    (uint32_t)((warp_n * 64 + np * 16 + b_row) * 128 + kbyte + b_cb));
                uint32_t bh[4], bl[4];
                LDSM_X4(bh[0], bh[1], bh[2], bh[3], smBhi + off);
                LDSM_X4(bl[0], bl[1], bl[2], bl[3], smBlo + off);
#pragma unroll
                for (int mt = 0; mt < 4; mt++) {
                    float* c0 = c[mt][2 * np];
                    float* c1 = c[mt][2 * np + 1];
                    MMA_BF16(c0, ahi[mt], bh[0], bh[1]);
                    MMA_BF16(c0, alo[mt], bh[0], bh[1]);
                    MMA_BF16(c0, ahi[mt], bl[0], bl[1]);
                    MMA_BF16(c1, ahi[mt], bh[2], bh[3]);
                    MMA_BF16(c1, alo[mt], bh[2], bh[3]);
                    MMA_BF16(c1, ahi[mt], bl[2], bl[3]);
                }
            }
        }
        __syncthreads();
    }

    // ---- epilogue ----
#pragma unroll
    for (int mt = 0; mt < 4; mt++) {
#pragma unroll
        for (int half = 0; half < 2; half++) {
            const int m = by * 128 + warp_m * 64 + mt * 16 + half * 8 + (lane >> 2);
            if (mode == 0) {
                const int l = m >> 2;
                const int nb = m & 3;
                const int sec = bx >> 2;    // 4 x 256-wide tiles per 1024 section
#pragma unroll
                for (int nt = 0; nt < 8; nt++) {
                    const int o = bx * 256 + warp_n * 64 + nt * 8 + 2 * (lane & 3);
                    const int h = (o & 1023) >> 6;
                    const int d = o & 63;
                    const size_t idx =
                        ((size_t)(nb * NH + h) * L_SEQ + l) * DH + d;
                    float v0 = c[mt][nt][half * 2];
                    float v1 = c[mt][nt][half * 2 + 1];
                    if (sec == 0) { v0 *= 0.125f; v1 *= 0.125f; }
                    uint32_t hi, lo;
                    pack_hilo(v0, v1, hi, lo);
                    if (sec == 0) {
                        *(uint32_t*)(g_qhi + idx) = hi;
                        *(uint32_t*)(g_qlo + idx) = lo;
                    } else if (sec == 1) {
                        *(uint32_t*)(g_khi + idx) = hi;
                        *(uint32_t*)(g_klo + idx) = lo;
                    } else {
                        *(uint32_t*)(g_vhi + idx) = hi;
                        *(uint32_t*)(g_vlo + idx) = lo;
                    }
                }
            } else {
                float* row = out + (size_t)m * EMB + bx * 256 + warp_n * 64
                             + 2 * (lane & 3);
#pragma unroll
                for (int nt = 0; nt < 8; nt++) {
                    float2 v = make_float2(c[mt][nt][half * 2],
                                           c[mt][nt][half * 2 + 1]);
                    *(float2*)(row + nt * 8) = v;
                }
            }
        }
    }
}

// ---------------------------------------------------------------------------
// Kernel 2: causal flash attention on HMMA (bf16 split, fp32 softmax).
// CTA = (head, 128 q rows), 8 warps x 16 rows, 64-key tiles double-buffered.
// Heaviest q-tiles launch first (gridDim.y reversed).
// ---------------------------------------------------------------------------
#define AT_TILE 8192                  // 64 rows x 128 B
#define AT_STAGE (4 * AT_TILE)        // Khi, Klo, Vhi, Vlo
#define ATTN_SMEM_BYTES (2 * AT_STAGE)

__device__ __forceinline__ void attn_load_stage(
    uint32_t smst,
    const __nv_bfloat16* Khi, const __nv_bfloat16* Klo,
    const __nv_bfloat16* Vhi, const __nv_bfloat16* Vlo,
    int kbase, int tid)
{
    const __nv_bfloat16* srcs[4] = {Khi, Klo, Vhi, Vlo};
#pragma unroll
    for (int t = 0; t < 4; t++) {
#pragma unroll
        for (int it = 0; it < 2; it++) {
            const int idx = it * 256 + tid;
            const int row = idx >> 3;
            const int cc = idx & 7;
            const uint32_t off = (uint32_t)(row * 128 + cc * 16);
            CP_ASYNC16(smst + t * AT_TILE + SWZ128(off),
                       srcs[t] + (size_t)(kbase + row) * DH + cc * 8);
        }
    }
    CP_ASYNC_COMMIT();
}

__global__ __launch_bounds__(256) void attn_hmma_kernel()
{
    extern __shared__ __align__(1024) char sm[];
    const uint32_t smb = smem_u32(sm);

    const int tid = threadIdx.x;
    const int wid = tid >> 5;
    const int lane = tid & 31;
    const int head = blockIdx.x;                 // 0..63
    const int bqt  = (int)gridDim.y - 1 - (int)blockIdx.y;  // heaviest first
    const int qbase = bqt * 128;

    const size_t hoff = (size_t)head * L_SEQ * DH;
    const __nv_bfloat16* Qhi = g_qhi + hoff;
    const __nv_bfloat16* Qlo = g_qlo + hoff;
    const __nv_bfloat16* Khi = g_khi + hoff;
    const __nv_bfloat16* Klo = g_klo + hoff;
    const __nv_bfloat16* Vhi = g_vhi + hoff;
    const __nv_bfloat16* Vlo = g_vlo + hoff;

    // Q fragments (direct LDG, once per CTA)
    const int r0 = qbase + wid * 16 + (lane >> 2);
    uint32_t qh[4][4], ql[4][4];
#pragma unroll
    for (int kc = 0; kc < 4; kc++) {
        const int d0 = kc * 16 + 2 * (lane & 3);
        qh[kc][0] = *(const uint32_t*)(Qhi + (size_t)r0 * DH + d0);
        qh[kc][1] = *(const uint32_t*)(Qhi + (size_t)(r0 + 8) * DH + d0);
        qh[kc][2] = *(const uint32_t*)(Qhi + (size_t)r0 * DH + d0 + 8);
        qh[kc][3] = *(const uint32_t*)(Qhi + (size_t)(r0 + 8) * DH + d0 + 8);
        ql[kc][0] = *(const uint32_t*)(Qlo + (size_t)r0 * DH + d0);
        ql[kc][1] = *(const uint32_t*)(Qlo + (size_t)(r0 + 8) * DH + d0);
        ql[kc][2] = *(const uint32_t*)(Qlo + (size_t)r0 * DH + d0 + 8);
        ql[kc][3] = *(const uint32_t*)(Qlo + (size_t)(r0 + 8) * DH + d0 + 8);
    }

    float o[8][4];
#pragma unroll
    for (int t = 0; t < 8; t++)
#pragma unroll
        for (int i = 0; i < 4; i++) o[t][i] = 0.0f;
    float m0 = -1e30f, m1 = -1e30f, l0 = 0.0f, l1 = 0.0f;

    const int b_row = (lane & 7) + ((lane >> 4) << 3);
    const int b_cb  = ((lane >> 3) & 1) * 16;
    const int v_row = ((lane >> 3) & 1) * 8 + (lane & 7);
    const int v_cb  = ((lane >> 4) & 1) * 16;

    const int nkt = qbase / 64 + 2;
    attn_load_stage(smb, Khi, Klo, Vhi, Vlo, 0, tid);

    for (int kt = 0; kt < nkt; kt++) {
        if (kt + 1 < nkt)
            attn_load_stage(smb + ((kt + 1) & 1) * AT_STAGE,
                            Khi, Klo, Vhi, Vlo, (kt + 1) * 64, tid);
        if (kt + 1 < nkt) { CP_ASYNC_WAIT(1); } else { CP_ASYNC_WAIT(0); }
        __syncthreads();

        const uint32_t sKh = smb + (kt & 1) * AT_STAGE;
        const uint32_t sKl = sKh + AT_TILE;
        const uint32_t sVh = sKh + 2 * AT_TILE;
        const uint32_t sVl = sKh + 3 * AT_TILE;

        // ---- S = Q K^T (3-pass split) ----
        float c[8][4];
#pragma unroll
        for (int t = 0; t < 8; t++)
#pragma unroll
            for (int i = 0; i < 4; i++) c[t][i] = 0.0f;

#pragma unroll
        for (int ng = 0; ng < 4; ng++) {
#pragma unroll
            for (int kc = 0; kc < 4; kc++) {
                const uint32_t off =
                    (uint32_t)((ng * 16 + b_row) * 128 + kc * 32 + b_cb);
                uint32_t bh[4], bl[4];
                LDSM_X4(bh[0], bh[1], bh[2], bh[3], sKh + SWZ128(off));
                LDSM_X4(bl[0], bl[1], bl[2], bl[3], sKl + SWZ128(off));
                MMA_BF16(c[2 * ng],     qh[kc], bh[0], bh[1]);
                MMA_BF16(c[2 * ng],     ql[kc], bh[0], bh[1]);
                MMA_BF16(c[2 * ng],     qh[kc], bl[0], bl[1]);
                MMA_BF16(c[2 * ng + 1], qh[kc], bh[2], bh[3]);
                MMA_BF16(c[2 * ng + 1], ql[kc], bh[2], bh[3]);
                MMA_BF16(c[2 * ng + 1], qh[kc], bl[2], bl[3]);
            }
        }

        // ---- causal mask (boundary tiles only) ----
        const int kb = kt * 64;
        if (kb + 63 > r0) {
#pragma unroll
            for (int t = 0; t < 8; t++) {
                const int col = kb + t * 8 + 2 * (lane & 3);
                if (col > r0)         c[t][0] = -1e30f;
                if (col + 1 > r0)     c[t][1] = -1e30f;
                if (col > r0 + 8)     c[t][2] = -1e30f;
                if (col + 1 > r0 + 8) c[t][3] = -1e30f;
            }
        }

        // ---- online softmax ----
        float mx0 = -1e30f, mx1 = -1e30f;
#pragma unroll
        for (int t = 0; t < 8; t++) {
            mx0 = fmaxf(mx0, fmaxf(c[t][0], c[t][1]));
            mx1 = fmaxf(mx1, fmaxf(c[t][2], c[t][3]));
        }
        mx0 = fmaxf(mx0, __shfl_xor_sync(0xffffffffu, mx0, 1));
        mx0 = fmaxf(mx0, __shfl_xor_sync(0xffffffffu, mx0, 2));
        mx1 = fmaxf(mx1, __shfl_xor_sync(0xffffffffu, mx1, 1));
        mx1 = fmaxf(mx1, __shfl_xor_sync(0xffffffffu, mx1, 2));

        const float mn0 = fmaxf(m0, mx0);
        const float mn1 = fmaxf(m1, mx1);
        const float corr0 = __expf(m0 - mn0);
        const float corr1 = __expf(m1 - mn1);
        m0 = mn0; m1 = mn1;

        float rs0 = 0.0f, rs1 = 0.0f;
#pragma unroll
        for (int t = 0; t < 8; t++) {
            c[t][0] = __expf(c[t][0] - mn0); rs0 += c[t][0];
            c[t][1] = __expf(c[t][1] - mn0); rs0 += c[t][1];
            c[t][2] = __expf(c[t][2] - mn1); rs1 += c[t][2];
            c[t][3] = __expf(c[t][3] - mn1); rs1 += c[t][3];
        }
        rs0 += __shfl_xor_sync(0xffffffffu, rs0, 1);
        rs0 += __shfl_xor_sync(0xffffffffu, rs0, 2);
        rs1 += __shfl_xor_sync(0xffffffffu, rs1, 1);
        rs1 += __shfl_xor_sync(0xffffffffu, rs1, 2);
        l0 = l0 * corr0 + rs0;
        l1 = l1 * corr1 + rs1;

#pragma unroll
        for (int t = 0; t < 8; t++) {
            o[t][0] *= corr0; o[t][1] *= corr0;
            o[t][2] *= corr1; o[t][3] *= corr1;
        }

        // ---- O += P V (3-pass split), P re-packed in-register ----
#pragma unroll
        for (int kc = 0; kc < 4; kc++) {
            uint32_t ah[4], al[4];
            pack_hilo(c[2 * kc][0],     c[2 * kc][1],     ah[0], al[0]);
            pack_hilo(c[2 * kc][2],     c[2 * kc][3],     ah[1], al[1]);
            pack_hilo(c[2 * kc + 1][0], c[2 * kc + 1][1], ah[2], al[2]);
            pack_hilo(c[2 * kc + 1][2], c[2 * kc + 1][3], ah[3], al[3]);
#pragma unroll
            for (int ng = 0; ng < 4; ng++) {
                const uint32_t off =
                    (uint32_t)((kc * 16 + v_row) * 128 + ng * 32 + v_cb);
                uint32_t vh[4], vl[4];
                LDSM_X4T(vh[0], vh[1], vh[2], vh[3], sVh + SWZ128(off));
                LDSM_X4T(vl[0], vl[1], vl[2], vl[3], sVl + SWZ128(off));
                MMA_BF16(o[2 * ng],     ah, vh[0], vh[1]);
                MMA_BF16(o[2 * ng],     al, vh[0], vh[1]);
                MMA_BF16(o[2 * ng],     ah, vl[0], vl[1]);
                MMA_BF16(o[2 * ng + 1], ah, vh[2], vh[3]);
                MMA_BF16(o[2 * ng + 1], al, vh[2], vh[3]);
                MMA_BF16(o[2 * ng + 1], ah, vl[2], vl[3]);
            }
        }
        __syncthreads();
    }

    // ---- epilogue: normalize, split to bf16 ctx [L][N][E] ----
    const float inv0 = 1.0f / l0;
    const float inv1 = 1.0f / l1;
    const int nb = head >> 4;
    const int hh = head & 15;
    const size_t base0 =
        ((size_t)r0 * N_BATCH + nb) * EMB + hh * DH + 2 * (lane & 3);
    const size_t base1 = base0 + (size_t)8 * N_BATCH * EMB;
#pragma unroll
    for (int t = 0; t < 8; t++) {
        uint32_t hi, lo;
        pack_hilo(o[t][0] * inv0, o[t][1] * inv0, hi, lo);
        *(uint32_t*)(g_ctxhi + base0 + t * 8) = hi;
        *(uint32_t*)(g_ctxlo + base0 + t * 8) = lo;
        pack_hilo(o[t][2] * inv1, o[t][3] * inv1, hi, lo);
        *(uint32_t*)(g_ctxhi + base1 + t * 8) = hi;
        *(uint32_t*)(g_ctxlo + base1 + t * 8) = lo;
    }
}

// ---------------------------------------------------------------------------
extern "C" void kernel_launch(void* const* d_in, const int* in_sizes, int n_in,
                              void* d_out, int out_size)
{
    const float* x    = (const float*)d_in[0];   // [L, N, E]
    const float* wqkv = (const float*)d_in[1];   // [3E, E]
    const float* wout = (const float*)d_in[2];   // [E, E]
    float* out = (float*)d_out;                  // [L, N, E]

    cudaFuncSetAttribute(tc_gemm_kernel,
                         cudaFuncAttributeMaxDynamicSharedMemorySize,
                         GEMM_SMEM_BYTES);
    cudaFuncSetAttribute(attn_hmma_kernel,
                         cudaFuncAttributeMaxDynamicSharedMemorySize,
                         ATTN_SMEM_BYTES);

    __nv_bfloat16 *xhi, *xlo, *whi, *wlo, *ohi, *olo, *chi, *clo;
    cudaGetSymbolAddress((void**)&xhi, g_xhi);
    cudaGetSymbolAddress((void**)&xlo, g_xlo);
    cudaGetSymbolAddress((void**)&whi, g_wqkvhi);
    cudaGetSymbolAddress((void**)&wlo, g_wqkvlo);
    cudaGetSymbolAddress((void**)&ohi, g_wouthi);
    cudaGetSymbolAddress((void**)&olo, g_woutlo);
    cudaGetSymbolAddress((void**)&chi, g_ctxhi);
    cudaGetSymbolAddress((void**)&clo, g_ctxlo);

    split_kernel<<<1024, 256>>>(x, xhi, xlo, M_ROWS * EMB);
    split_kernel<<<1024, 256>>>(wqkv, whi, wlo, 3 * EMB * EMB);
    split_kernel<<<512, 256>>>(wout, ohi, olo, EMB * EMB);

    tc_gemm_kernel<<<dim3(12, 64), 256, GEMM_SMEM_BYTES>>>(
        xhi, xlo, whi, wlo, nullptr, 0);

    attn_hmma_kernel<<<dim3(64, 16), 256, ATTN_SMEM_BYTES>>>();

    tc_gemm_kernel<<<dim3(4, 64), 256, GEMM_SMEM_BYTES>>>(
        chi, clo, ohi, olo, out, 1);
}

// round 6
// speedup vs baseline: 7.6687x; 2.3864x over previous
#include <cuda_runtime.h>
#include <cuda_fp16.h>
#include <cstdint>
#include <math.h>

// Problem constants
#define L_SEQ   2048
#define N_BATCH 4
#define EMB     1024
#define NH      16
#define DH      64
#define NHEADS  (N_BATCH * NH)      // 64
#define M_ROWS  (L_SEQ * N_BATCH)   // 8192

// ---------------------------------------------------------------------------
// Scratch (allocation-free: __device__ globals) — all fp16 single-precision-path
// ---------------------------------------------------------------------------
__device__ __half g_q16[(size_t)NHEADS * L_SEQ * DH];   // pre-scaled by 0.125
__device__ __half g_k16[(size_t)NHEADS * L_SEQ * DH];
__device__ __half g_v16[(size_t)NHEADS * L_SEQ * DH];
__device__ __half g_x16[(size_t)M_ROWS * EMB];
__device__ __half g_wqkv16[(size_t)3 * EMB * EMB];
__device__ __half g_wout16[(size_t)EMB * EMB];
__device__ __half g_ctx16[(size_t)M_ROWS * EMB];

// ---------------------------------------------------------------------------
// PTX helpers (portable ISA: cp.async / ldmatrix / mma.sync)
// ---------------------------------------------------------------------------
__device__ __forceinline__ uint32_t smem_u32(const void* p) {
    uint32_t a;
    asm("{ .reg .u64 t; cvta.to.shared.u64 t, %1; cvt.u32.u64 %0, t; }"
        : "=r"(a) : "l"(p));
    return a;
}

#define SWZ128(o) ((o) ^ (((o) >> 3) & 0x70))

#define CP_ASYNC16(dst, src) \
    asm volatile("cp.async.cg.shared.global [%0], [%1], 16;" \
                 :: "r"(dst), "l"(src) : "memory")
#define CP_ASYNC_COMMIT()  asm volatile("cp.async.commit_group;" ::: "memory")
#define CP_ASYNC_WAIT(n)   asm volatile("cp.async.wait_group %0;" :: "n"(n) : "memory")

#define LDSM_X4(r0, r1, r2, r3, addr) \
    asm volatile("ldmatrix.sync.aligned.m8n8.x4.shared.b16 {%0,%1,%2,%3}, [%4];" \
                 : "=r"(r0), "=r"(r1), "=r"(r2), "=r"(r3) : "r"(addr))

#define LDSM_X4T(r0, r1, r2, r3, addr) \
    asm volatile("ldmatrix.sync.aligned.m8n8.x4.trans.shared.b16 {%0,%1,%2,%3}, [%4];" \
                 : "=r"(r0), "=r"(r1), "=r"(r2), "=r"(r3) : "r"(addr))

#define MMA_F16(c, a, b0, b1) \
    asm volatile("mma.sync.aligned.m16n8k16.row.col.f32.f16.f16.f32 " \
                 "{%0,%1,%2,%3}, {%4,%5,%6,%7}, {%8,%9}, {%0,%1,%2,%3};" \
                 : "+f"((c)[0]), "+f"((c)[1]), "+f"((c)[2]), "+f"((c)[3]) \
                 : "r"((a)[0]), "r"((a)[1]), "r"((a)[2]), "r"((a)[3]), \
                   "r"(b0), "r"(b1))

__device__ __forceinline__ uint32_t pack2h(float f0, float f1) {
    __half2 h = __floats2half2_rn(f0, f1);
    return *reinterpret_cast<uint32_t*>(&h);
}

// ---------------------------------------------------------------------------
// Kernel 0: fp32 -> fp16 quantize
// ---------------------------------------------------------------------------
__global__ __launch_bounds__(256) void quant_kernel(
    const float* __restrict__ src, __half* __restrict__ dst, int n)
{
    for (int i = blockIdx.x * blockDim.x + threadIdx.x; i < n;
         i += gridDim.x * blockDim.x)
        dst[i] = __float2half(src[i]);
}

// ---------------------------------------------------------------------------
// HMMA GEMM (fp16 1-pass): C[m, o] = sum_k A[m,k] * B[o,k]
// CTA 128x128, K-chunk 64 (128B SW128 rows), double-buffered cp.async,
// 8 warps 4(M)x2(N), warp tile 32x64.
// mode 0: QKV scatter epilogue -> fp16 q(scaled)/k/v [head][l][d]
// mode 1: fp32 rows into `out`
// ---------------------------------------------------------------------------
#define TILE_B 16384                  // 128 rows x 128 B
#define STAGE_B (2 * TILE_B)          // A + B = 32 KB
#define GEMM_SMEM_BYTES (2 * STAGE_B) // 64 KB

__device__ __forceinline__ void gemm_load_stage(
    uint32_t smst, const __half* A, const __half* B,
    int arow0, int brow0, int k0, int tid)
{
#pragma unroll
    for (int r = 0; r < 4; r++) {
        const int idx = r * 256 + tid;
        const int row = idx >> 3;
        const int cc = idx & 7;
        const uint32_t off = SWZ128((uint32_t)(row * 128 + cc * 16));
        CP_ASYNC16(smst + off, A + (size_t)(arow0 + row) * EMB + k0 + cc * 8);
        CP_ASYNC16(smst + TILE_B + off,
                   B + (size_t)(brow0 + row) * EMB + k0 + cc * 8);
    }
    CP_ASYNC_COMMIT();
}

__global__ __launch_bounds__(256, 2) void tc_gemm_kernel(
    const __half* __restrict__ A, const __half* __restrict__ B,
    float* __restrict__ out, int mode)
{
    extern __shared__ __align__(1024) char sm[];
    const uint32_t smb = smem_u32(sm);

    const int tid = threadIdx.x;
    const int wid = tid >> 5;
    const int lane = tid & 31;
    const int warp_m = wid & 3;          // 0..3 (32 rows)
    const int warp_n = wid >> 2;         // 0..1 (64 cols)
    const int bx = blockIdx.x;
    const int by = blockIdx.y;

    float c[2][8][4];
#pragma unroll
    for (int mt = 0; mt < 2; mt++)
#pragma unroll
        for (int nt = 0; nt < 8; nt++)
#pragma unroll
            for (int i = 0; i < 4; i++) c[mt][nt][i] = 0.0f;

    const int a_row = lane & 15;
    const int a_cb  = (lane >> 4) * 16;
    const int b_row = (lane & 7) + ((lane >> 4) << 3);
    const int b_cb  = ((lane >> 3) & 1) * 16;

    gemm_load_stage(smb, A, B, by * 128, bx * 128, 0, tid);

    const int NCHUNK = EMB / 64;   // 16
    for (int ck = 0; ck < NCHUNK; ck++) {
        if (ck + 1 < NCHUNK)
            gemm_load_stage(smb + ((ck + 1) & 1) * STAGE_B, A, B,
                            by * 128, bx * 128, (ck + 1) * 64, tid);
        if (ck + 1 < NCHUNK) { CP_ASYNC_WAIT(1); } else { CP_ASYNC_WAIT(0); }
        __syncthreads();

        const uint32_t smA = smb + (ck & 1) * STAGE_B;
        const uint32_t smB = smA + TILE_B;

#pragma unroll
        for (int ks = 0; ks < 4; ks++) {
            const int kbyte = ks * 32;
            uint32_t a[2][4];
#pragma unroll
            for (int mt = 0; mt < 2; mt++) {
                const uint32_t off = SWZ128(
                    (uint32_t)((warp_m * 32 + mt * 16 + a_row) * 128 + kbyte + a_cb));
                LDSM_X4(a[mt][0], a[mt][1], a[mt][2], a[mt][3], smA + off);
            }
#pragma unroll
            for (int np = 0; np < 4; np++) {
                const uint32_t off = SWZ128(
                    (uint32_t)((warp_n * 64 + np * 16 + b_row) * 128 + kbyte + b_cb));
                uint32_t bh[4];
                LDSM_X4(bh[0], bh[1], bh[2], bh[3], smB + off);
#pragma unroll
                for (int mt = 0; mt < 2; mt++) {
                    MMA_F16(c[mt][2 * np],     a[mt], bh[0], bh[1]);
                    MMA_F16(c[mt][2 * np + 1], a[mt], bh[2], bh[3]);
                }
            }
        }
        __syncthreads();
    }

    // ---- epilogue ----
    const int mrow_base = by * 128 + warp_m * 32 + (lane >> 2);
    const int ncol_base = warp_n * 64 + 2 * (lane & 3);
#pragma unroll
    for (int mt = 0; mt < 2; mt++) {
#pragma unroll
        for (int half = 0; half < 2; half++) {
            const int m = mrow_base + mt * 16 + half * 8;
            if (mode == 0) {
                const int l = m >> 2;
                const int nb = m & 3;
                const int sec = bx >> 3;      // 0=q 1=k 2=v
#pragma unroll
                for (int nt = 0; nt < 8; nt++) {
                    const int o = bx * 128 + ncol_base + nt * 8;
                    const int h = (o & 1023) >> 6;
                    const int d = o & 63;
                    const size_t idx =
                        ((size_t)(nb * NH + h) * L_SEQ + l) * DH + d;
                    float v0 = c[mt][nt][half * 2];
                    float v1 = c[mt][nt][half * 2 + 1];
                    if (sec == 0) {
                        v0 *= 0.125f; v1 *= 0.125f;
                        *(uint32_t*)(g_q16 + idx) = pack2h(v0, v1);
                    } else if (sec == 1) {
                        *(uint32_t*)(g_k16 + idx) = pack2h(v0, v1);
                    } else {
                        *(uint32_t*)(g_v16 + idx) = pack2h(v0, v1);
                    }
                }
            } else {
                float* row = out + (size_t)m * EMB + bx * 128 + ncol_base;
#pragma unroll
                for (int nt = 0; nt < 8; nt++) {
                    float2 v = make_float2(c[mt][nt][half * 2],
                                           c[mt][nt][half * 2 + 1]);
                    *(float2*)(row + nt * 8) = v;
                }
            }
        }
    }
}

// ---------------------------------------------------------------------------
// Kernel 2: causal flash attention on fp16 HMMA (fp32 softmax).
// CTA = (head, 128 q rows), 8 warps x 16 rows, 64-key tiles double-buffered.
// Heaviest q-tiles launch first.
// ---------------------------------------------------------------------------
#define AT_TILE 8192                  // 64 rows x 128 B
#define AT_STAGE (2 * AT_TILE)        // K, V = 16 KB
#define ATTN_SMEM_BYTES (2 * AT_STAGE)

__device__ __forceinline__ void attn_load_stage(
    uint32_t smst, const __half* K, const __half* V, int kbase, int tid)
{
#pragma unroll
    for (int it = 0; it < 2; it++) {
        const int idx = it * 256 + tid;
        const int row = idx >> 3;
        const int cc = idx & 7;
        const uint32_t off = SWZ128((uint32_t)(row * 128 + cc * 16));
        CP_ASYNC16(smst + off, K + (size_t)(kbase + row) * DH + cc * 8);
        CP_ASYNC16(smst + AT_TILE + off,
                   V + (size_t)(kbase + row) * DH + cc * 8);
    }
    CP_ASYNC_COMMIT();
}

__global__ __launch_bounds__(256, 2) void attn_hmma_kernel()
{
    extern __shared__ __align__(1024) char sm[];
    const uint32_t smb = smem_u32(sm);

    const int tid = threadIdx.x;
    const int wid = tid >> 5;
    const int lane = tid & 31;
    const int head = blockIdx.x;                            // 0..63
    const int bqt  = (int)gridDim.y - 1 - (int)blockIdx.y;  // heaviest first
    const int qbase = bqt * 128;

    const size_t hoff = (size_t)head * L_SEQ * DH;
    const __half* Q = g_q16 + hoff;
    const __half* K = g_k16 + hoff;
    const __half* V = g_v16 + hoff;

    // Q fragments (direct LDG, once per CTA)
    const int r0 = qbase + wid * 16 + (lane >> 2);
    uint32_t qh[4][4];
#pragma unroll
    for (int kc = 0; kc < 4; kc++) {
        const int d0 = kc * 16 + 2 * (lane & 3);
        qh[kc][0] = *(const uint32_t*)(Q + (size_t)r0 * DH + d0);
        qh[kc][1] = *(const uint32_t*)(Q + (size_t)(r0 + 8) * DH + d0);
        qh[kc][2] = *(const uint32_t*)(Q + (size_t)r0 * DH + d0 + 8);
        qh[kc][3] = *(const uint32_t*)(Q + (size_t)(r0 + 8) * DH + d0 + 8);
    }

    float o[8][4];
#pragma unroll
    for (int t = 0; t < 8; t++)
#pragma unroll
        for (int i = 0; i < 4; i++) o[t][i] = 0.0f;
    float m0 = -1e30f, m1 = -1e30f, l0 = 0.0f, l1 = 0.0f;

    const int b_row = (lane & 7) + ((lane >> 4) << 3);
    const int b_cb  = ((lane >> 3) & 1) * 16;
    const int v_row = ((lane >> 3) & 1) * 8 + (lane & 7);
    const int v_cb  = ((lane >> 4) & 1) * 16;

    const int nkt = qbase / 64 + 2;
    attn_load_stage(smb, K, V, 0, tid);

    for (int kt = 0; kt < nkt; kt++) {
        if (kt + 1 < nkt)
            attn_load_stage(smb + ((kt + 1) & 1) * AT_STAGE,
                            K, V, (kt + 1) * 64, tid);
        if (kt + 1 < nkt) { CP_ASYNC_WAIT(1); } else { CP_ASYNC_WAIT(0); }
        __syncthreads();

        const uint32_t sK = smb + (kt & 1) * AT_STAGE;
        const uint32_t sV = sK + AT_TILE;

        // ---- S = Q K^T ----
        float c[8][4];
#pragma unroll
        for (int t = 0; t < 8; t++)
#pragma unroll
            for (int i = 0; i < 4; i++) c[t][i] = 0.0f;

#pragma unroll
        for (int ng = 0; ng < 4; ng++) {
#pragma unroll
            for (int kc = 0; kc < 4; kc++) {
                const uint32_t off = SWZ128(
                    (uint32_t)((ng * 16 + b_row) * 128 + kc * 32 + b_cb));
                uint32_t bh[4];
                LDSM_X4(bh[0], bh[1], bh[2], bh[3], sK + off);
                MMA_F16(c[2 * ng],     qh[kc], bh[0], bh[1]);
                MMA_F16(c[2 * ng + 1], qh[kc], bh[2], bh[3]);
            }
        }

        // ---- causal mask (boundary tiles only) ----
        const int kb = kt * 64;
        if (kb + 63 > r0) {
#pragma unroll
            for (int t = 0; t < 8; t++) {
                const int col = kb + t * 8 + 2 * (lane & 3);
                if (col > r0)         c[t][0] = -1e30f;
                if (col + 1 > r0)     c[t][1] = -1e30f;
                if (col > r0 + 8)     c[t][2] = -1e30f;
                if (col + 1 > r0 + 8) c[t][3] = -1e30f;
            }
        }

        // ---- online softmax ----
        float mx0 = -1e30f, mx1 = -1e30f;
#pragma unroll
        for (int t = 0; t < 8; t++) {
            mx0 = fmaxf(mx0, fmaxf(c[t][0], c[t][1]));
            mx1 = fmaxf(mx1, fmaxf(c[t][2], c[t][3]));
        }
        mx0 = fmaxf(mx0, __shfl_xor_sync(0xffffffffu, mx0, 1));
        mx0 = fmaxf(mx0, __shfl_xor_sync(0xffffffffu, mx0, 2));
        mx1 = fmaxf(mx1, __shfl_xor_sync(0xffffffffu, mx1, 1));
        mx1 = fmaxf(mx1, __shfl_xor_sync(0xffffffffu, mx1, 2));

        const float mn0 = fmaxf(m0, mx0);
        const float mn1 = fmaxf(m1, mx1);
        const float corr0 = __expf(m0 - mn0);
        const float corr1 = __expf(m1 - mn1);
        m0 = mn0; m1 = mn1;

        float rs0 = 0.0f, rs1 = 0.0f;
#pragma unroll
        for (int t = 0; t < 8; t++) {
            c[t][0] = __expf(c[t][0] - mn0); rs0 += c[t][0];
            c[t][1] = __expf(c[t][1] - mn0); rs0 += c[t][1];
            c[t][2] = __expf(c[t][2] - mn1); rs1 += c[t][2];
            c[t][3] = __expf(c[t][3] - mn1); rs1 += c[t][3];
        }
        rs0 += __shfl_xor_sync(0xffffffffu, rs0, 1);
        rs0 += __shfl_xor_sync(0xffffffffu, rs0, 2);
        rs1 += __shfl_xor_sync(0xffffffffu, rs1, 1);
        rs1 += __shfl_xor_sync(0xffffffffu, rs1, 2);
        l0 = l0 * corr0 + rs0;
        l1 = l1 * corr1 + rs1;

#pragma unroll
        for (int t = 0; t < 8; t++) {
            o[t][0] *= corr0; o[t][1] *= corr0;
            o[t][2] *= corr1; o[t][3] *= corr1;
        }

        // ---- O += P V, P packed fp16 in-register ----
#pragma unroll
        for (int kc = 0; kc < 4; kc++) {
            uint32_t ah[4];
            ah[0] = pack2h(c[2 * kc][0],     c[2 * kc][1]);
            ah[1] = pack2h(c[2 * kc][2],     c[2 * kc][3]);
            ah[2] = pack2h(c[2 * kc + 1][0], c[2 * kc + 1][1]);
            ah[3] = pack2h(c[2 * kc + 1][2], c[2 * kc + 1][3]);
#pragma unroll
            for (int ng = 0; ng < 4; ng++) {
                const uint32_t off = SWZ128(
                    (uint32_t)((kc * 16 + v_row) * 128 + ng * 32 + v_cb));
                uint32_t vh[4];
                LDSM_X4T(vh[0], vh[1], vh[2], vh[3], sV + off);
                MMA_F16(o[2 * ng],     ah, vh[0], vh[1]);
                MMA_F16(o[2 * ng + 1], ah, vh[2], vh[3]);
            }
        }
        __syncthreads();
    }

    // ---- epilogue: normalize, fp16 ctx [L][N][E] ----
    const float inv0 = 1.0f / l0;
    const float inv1 = 1.0f / l1;
    const int nb = head >> 4;
    const int hh = head & 15;
    const size_t base0 =
        ((size_t)r0 * N_BATCH + nb) * EMB + hh * DH + 2 * (lane & 3);
    const size_t base1 = base0 + (size_t)8 * N_BATCH * EMB;
#pragma unroll
    for (int t = 0; t < 8; t++) {
        *(uint32_t*)(g_ctx16 + base0 + t * 8) =
            pack2h(o[t][0] * inv0, o[t][1] * inv0);
        *(uint32_t*)(g_ctx16 + base1 + t * 8) =
            pack2h(o[t][2] * inv1, o[t][3] * inv1);
    }
}

// ---------------------------------------------------------------------------
extern "C" void kernel_launch(void* const* d_in, const int* in_sizes, int n_in,
                              void* d_out, int out_size)
{
    const float* x    = (const float*)d_in[0];   // [L, N, E]
    const float* wqkv = (const float*)d_in[1];   // [3E, E]
    const float* wout = (const float*)d_in[2];   // [E, E]
    float* out = (float*)d_out;                  // [L, N, E]

    cudaFuncSetAttribute(tc_gemm_kernel,
                         cudaFuncAttributeMaxDynamicSharedMemorySize,
                         GEMM_SMEM_BYTES);
    cudaFuncSetAttribute(attn_hmma_kernel,
                         cudaFuncAttributeMaxDynamicSharedMemorySize,
                         ATTN_SMEM_BYTES);

    __half *x16, *w16, *o16;
    cudaGetSymbolAddress((void**)&x16, g_x16);
    cudaGetSymbolAddress((void**)&w16, g_wqkv16);
    cudaGetSymbolAddress((void**)&o16, g_wout16);

    quant_kernel<<<512, 256>>>(x, x16, M_ROWS * EMB);
    quant_kernel<<<512, 256>>>(wqkv, w16, 3 * EMB * EMB);
    quant_kernel<<<256, 256>>>(wout, o16, EMB * EMB);

    tc_gemm_kernel<<<dim3(24, 64), 256, GEMM_SMEM_BYTES>>>(
        x16, w16, nullptr, 0);

    attn_hmma_kernel<<<dim3(64, 16), 256, ATTN_SMEM_BYTES>>>();

    __half* ctx16;
    cudaGetSymbolAddress((void**)&ctx16, g_ctx16);
    tc_gemm_kernel<<<dim3(8, 64), 256, GEMM_SMEM_BYTES>>>(
        ctx16, o16, out, 1);
}

// round 7
// speedup vs baseline: 8.2600x; 1.0771x over previous
#include <cuda_runtime.h>
#include <cuda_fp16.h>
#include <cstdint>
#include <math.h>

// Problem constants
#define L_SEQ   2048
#define N_BATCH 4
#define EMB     1024
#define NH      16
#define DH      64
#define NHEADS  (N_BATCH * NH)      // 64
#define M_ROWS  (L_SEQ * N_BATCH)   // 8192

// ---------------------------------------------------------------------------
// Scratch (allocation-free: __device__ globals) — fp16 single-pass path
// ---------------------------------------------------------------------------
__device__ __half g_q16[(size_t)NHEADS * L_SEQ * DH];   // pre-scaled by 0.125
__device__ __half g_k16[(size_t)NHEADS * L_SEQ * DH];
__device__ __half g_v16[(size_t)NHEADS * L_SEQ * DH];
__device__ __half g_x16[(size_t)M_ROWS * EMB];
__device__ __half g_wqkv16[(size_t)3 * EMB * EMB];
__device__ __half g_wout16[(size_t)EMB * EMB];
__device__ __half g_ctx16[(size_t)M_ROWS * EMB];

// ---------------------------------------------------------------------------
// PTX helpers (portable ISA: cp.async / ldmatrix / mma.sync)
// ---------------------------------------------------------------------------
__device__ __forceinline__ uint32_t smem_u32(const void* p) {
    uint32_t a;
    asm("{ .reg .u64 t; cvta.to.shared.u64 t, %1; cvt.u32.u64 %0, t; }"
        : "=r"(a) : "l"(p));
    return a;
}

#define SWZ128(o) ((o) ^ (((o) >> 3) & 0x70))

#define CP_ASYNC16(dst, src) \
    asm volatile("cp.async.cg.shared.global [%0], [%1], 16;" \
                 :: "r"(dst), "l"(src) : "memory")
#define CP_ASYNC_COMMIT()  asm volatile("cp.async.commit_group;" ::: "memory")
#define CP_ASYNC_WAIT(n)   asm volatile("cp.async.wait_group %0;" :: "n"(n) : "memory")

#define LDSM_X4(r0, r1, r2, r3, addr) \
    asm volatile("ldmatrix.sync.aligned.m8n8.x4.shared.b16 {%0,%1,%2,%3}, [%4];" \
                 : "=r"(r0), "=r"(r1), "=r"(r2), "=r"(r3) : "r"(addr))

#define LDSM_X4T(r0, r1, r2, r3, addr) \
    asm volatile("ldmatrix.sync.aligned.m8n8.x4.trans.shared.b16 {%0,%1,%2,%3}, [%4];" \
                 : "=r"(r0), "=r"(r1), "=r"(r2), "=r"(r3) : "r"(addr))

#define MMA_F16(c, a, b0, b1) \
    asm volatile("mma.sync.aligned.m16n8k16.row.col.f32.f16.f16.f32 " \
                 "{%0,%1,%2,%3}, {%4,%5,%6,%7}, {%8,%9}, {%0,%1,%2,%3};" \
                 : "+f"((c)[0]), "+f"((c)[1]), "+f"((c)[2]), "+f"((c)[3]) \
                 : "r"((a)[0]), "r"((a)[1]), "r"((a)[2]), "r"((a)[3]), \
                   "r"(b0), "r"(b1))

__device__ __forceinline__ uint32_t pack2h(float f0, float f1) {
    __half2 h = __floats2half2_rn(f0, f1);
    return *reinterpret_cast<uint32_t*>(&h);
}

// ---------------------------------------------------------------------------
// Kernel 0: fused fp32 -> fp16 quantize of x, wqkv, wout (one launch)
// ---------------------------------------------------------------------------
#define N_X   (M_ROWS * EMB)          // 8388608
#define N_WQ  (3 * EMB * EMB)         // 3145728
#define N_WO  (EMB * EMB)             // 1048576
#define N_ALL (N_X + N_WQ + N_WO)

__global__ __launch_bounds__(256) void quant_all_kernel(
    const float* __restrict__ x, const float* __restrict__ wqkv,
    const float* __restrict__ wout)
{
    for (int i = blockIdx.x * blockDim.x + threadIdx.x; i < N_ALL;
         i += gridDim.x * blockDim.x) {
        if (i < N_X) {
            g_x16[i] = __float2half(x[i]);
        } else if (i < N_X + N_WQ) {
            const int j = i - N_X;
            g_wqkv16[j] = __float2half(wqkv[j]);
        } else {
            const int j = i - N_X - N_WQ;
            g_wout16[j] = __float2half(wout[j]);
        }
    }
}

// ---------------------------------------------------------------------------
// HMMA GEMM (fp16): C[m, o] = sum_k A[m,k] * B[o,k]
// CTA 128x128, K-chunk 64 (128B SW128 rows), 3-stage cp.async pipeline,
// 8 warps 4(M)x2(N), warp tile 32x64. One __syncthreads per chunk.
// mode 0: QKV scatter epilogue -> fp16 q(scaled)/k/v [head][l][d]
// mode 1: fp32 rows into `out`
// ---------------------------------------------------------------------------
#define TILE_B 16384                  // 128 rows x 128 B
#define STAGE_B (2 * TILE_B)          // A + B = 32 KB
#define GEMM_STAGES 3
#define GEMM_SMEM_BYTES (GEMM_STAGES * STAGE_B)   // 96 KB

__device__ __forceinline__ void gemm_load_stage(
    uint32_t smst, const __half* A, const __half* B,
    int arow0, int brow0, int k0, int tid)
{
#pragma unroll
    for (int r = 0; r < 4; r++) {
        const int idx = r * 256 + tid;
        const int row = idx >> 3;
        const int cc = idx & 7;
        const uint32_t off = SWZ128((uint32_t)(row * 128 + cc * 16));
        CP_ASYNC16(smst + off, A + (size_t)(arow0 + row) * EMB + k0 + cc * 8);
        CP_ASYNC16(smst + TILE_B + off,
                   B + (size_t)(brow0 + row) * EMB + k0 + cc * 8);
    }
    CP_ASYNC_COMMIT();
}

__global__ __launch_bounds__(256, 2) void tc_gemm_kernel(
    const __half* __restrict__ A, const __half* __restrict__ B,
    float* __restrict__ out, int mode)
{
    extern __shared__ __align__(1024) char sm[];
    const uint32_t smb = smem_u32(sm);

    const int tid = threadIdx.x;
    const int wid = tid >> 5;
    const int lane = tid & 31;
    const int warp_m = wid & 3;
    const int warp_n = wid >> 2;
    const int bx = blockIdx.x;
    const int by = blockIdx.y;

    float c[2][8][4];
#pragma unroll
    for (int mt = 0; mt < 2; mt++)
#pragma unroll
        for (int nt = 0; nt < 8; nt++)
#pragma unroll
            for (int i = 0; i < 4; i++) c[mt][nt][i] = 0.0f;

    const int a_row = lane & 15;
    const int a_cb  = (lane >> 4) * 16;
    const int b_row = (lane & 7) + ((lane >> 4) << 3);
    const int b_cb  = ((lane >> 3) & 1) * 16;

    const int NCHUNK = EMB / 64;   // 16
    // prologue: stages 0 and 1
    gemm_load_stage(smb, A, B, by * 128, bx * 128, 0, tid);
    gemm_load_stage(smb + STAGE_B, A, B, by * 128, bx * 128, 64, tid);

    for (int ck = 0; ck < NCHUNK; ck++) {
        if (ck + 1 < NCHUNK) { CP_ASYNC_WAIT(1); } else { CP_ASYNC_WAIT(0); }
        __syncthreads();
        if (ck + 2 < NCHUNK)
            gemm_load_stage(smb + ((ck + 2) % GEMM_STAGES) * STAGE_B, A, B,
                            by * 128, bx * 128, (ck + 2) * 64, tid);

        const uint32_t smA = smb + (ck % GEMM_STAGES) * STAGE_B;
        const uint32_t smB = smA + TILE_B;

#pragma unroll
        for (int ks = 0; ks < 4; ks++) {
            const int kbyte = ks * 32;
            uint32_t a[2][4];
#pragma unroll
            for (int mt = 0; mt < 2; mt++) {
                const uint32_t off = SWZ128(
                    (uint32_t)((warp_m * 32 + mt * 16 + a_row) * 128 + kbyte + a_cb));
                LDSM_X4(a[mt][0], a[mt][1], a[mt][2], a[mt][3], smA + off);
            }
#pragma unroll
            for (int np = 0; np < 4; np++) {
                const uint32_t off = SWZ128(
                    (uint32_t)((warp_n * 64 + np * 16 + b_row) * 128 + kbyte + b_cb));
                uint32_t bh[4];
                LDSM_X4(bh[0], bh[1], bh[2], bh[3], smB + off);
#pragma unroll
                for (int mt = 0; mt < 2; mt++) {
                    MMA_F16(c[mt][2 * np],     a[mt], bh[0], bh[1]);
                    MMA_F16(c[mt][2 * np + 1], a[mt], bh[2], bh[3]);
                }
            }
        }
    }

    // ---- epilogue ----
    const int mrow_base = by * 128 + warp_m * 32 + (lane >> 2);
    const int ncol_base = warp_n * 64 + 2 * (lane & 3);
#pragma unroll
    for (int mt = 0; mt < 2; mt++) {
#pragma unroll
        for (int half = 0; half < 2; half++) {
            const int m = mrow_base + mt * 16 + half * 8;
            if (mode == 0) {
                const int l = m >> 2;
                const int nb = m & 3;
                const int sec = bx >> 3;      // 0=q 1=k 2=v
#pragma unroll
                for (int nt = 0; nt < 8; nt++) {
                    const int o = bx * 128 + ncol_base + nt * 8;
                    const int h = (o & 1023) >> 6;
                    const int d = o & 63;
                    const size_t idx =
                        ((size_t)(nb * NH + h) * L_SEQ + l) * DH + d;
                    float v0 = c[mt][nt][half * 2];
                    float v1 = c[mt][nt][half * 2 + 1];
                    if (sec == 0) {
                        v0 *= 0.125f; v1 *= 0.125f;
                        *(uint32_t*)(g_q16 + idx) = pack2h(v0, v1);
                    } else if (sec == 1) {
                        *(uint32_t*)(g_k16 + idx) = pack2h(v0, v1);
                    } else {
                        *(uint32_t*)(g_v16 + idx) = pack2h(v0, v1);
                    }
                }
            } else {
                float* row = out + (size_t)m * EMB + bx * 128 + ncol_base;
#pragma unroll
                for (int nt = 0; nt < 8; nt++) {
                    float2 v = make_float2(c[mt][nt][half * 2],
                                           c[mt][nt][half * 2 + 1]);
                    *(float2*)(row + nt * 8) = v;
                }
            }
        }
    }
}

// ---------------------------------------------------------------------------
// Kernel 2: causal flash attention on fp16 HMMA (fp32 softmax).
// CTA = (head, 128 q rows), 8 warps x 16 rows, 64-key tiles, 3-stage pipeline.
// Heaviest q-tiles launch first.
// ---------------------------------------------------------------------------
#define AT_TILE 8192                  // 64 rows x 128 B
#define AT_STAGE (2 * AT_TILE)        // K, V = 16 KB
#define AT_STAGES 3
#define ATTN_SMEM_BYTES (AT_STAGES * AT_STAGE)   // 48 KB

__device__ __forceinline__ void attn_load_stage(
    uint32_t smst, const __half* K, const __half* V, int kbase, int tid)
{
#pragma unroll
    for (int it = 0; it < 2; it++) {
        const int idx = it * 256 + tid;
        const int row = idx >> 3;
        const int cc = idx & 7;
        const uint32_t off = SWZ128((uint32_t)(row * 128 + cc * 16));
        CP_ASYNC16(smst + off, K + (size_t)(kbase + row) * DH + cc * 8);
        CP_ASYNC16(smst + AT_TILE + off,
                   V + (size_t)(kbase + row) * DH + cc * 8);
    }
    CP_ASYNC_COMMIT();
}

__global__ __launch_bounds__(256, 2) void attn_hmma_kernel()
{
    extern __shared__ __align__(1024) char sm[];
    const uint32_t smb = smem_u32(sm);

    const int tid = threadIdx.x;
    const int wid = tid >> 5;
    const int lane = tid & 31;
    const int head = blockIdx.x;                            // 0..63
    const int bqt  = (int)gridDim.y - 1 - (int)blockIdx.y;  // heaviest first
    const int qbase = bqt * 128;

    const size_t hoff = (size_t)head * L_SEQ * DH;
    const __half* Q = g_q16 + hoff;
    const __half* K = g_k16 + hoff;
    const __half* V = g_v16 + hoff;

    // Q fragments (direct LDG, once per CTA)
    const int r0 = qbase + wid * 16 + (lane >> 2);
    uint32_t qh[4][4];
#pragma unroll
    for (int kc = 0; kc < 4; kc++) {
        const int d0 = kc * 16 + 2 * (lane & 3);
        qh[kc][0] = *(const uint32_t*)(Q + (size_t)r0 * DH + d0);
        qh[kc][1] = *(const uint32_t*)(Q + (size_t)(r0 + 8) * DH + d0);
        qh[kc][2] = *(const uint32_t*)(Q + (size_t)r0 * DH + d0 + 8);
        qh[kc][3] = *(const uint32_t*)(Q + (size_t)(r0 + 8) * DH + d0 + 8);
    }

    float o[8][4];
#pragma unroll
    for (int t = 0; t < 8; t++)
#pragma unroll
        for (int i = 0; i < 4; i++) o[t][i] = 0.0f;
    float m0 = -1e30f, m1 = -1e30f, l0 = 0.0f, l1 = 0.0f;

    const int b_row = (lane & 7) + ((lane >> 4) << 3);
    const int b_cb  = ((lane >> 3) & 1) * 16;
    const int v_row = ((lane >> 3) & 1) * 8 + (lane & 7);
    const int v_cb  = ((lane >> 4) & 1) * 16;

    const int nkt = qbase / 64 + 2;
    attn_load_stage(smb, K, V, 0, tid);
    if (nkt > 1) attn_load_stage(smb + AT_STAGE, K, V, 64, tid);

    for (int kt = 0; kt < nkt; kt++) {
        if (kt + 1 < nkt) { CP_ASYNC_WAIT(1); } else { CP_ASYNC_WAIT(0); }
        __syncthreads();
        if (kt + 2 < nkt)
            attn_load_stage(smb + ((kt + 2) % AT_STAGES) * AT_STAGE,
                            K, V, (kt + 2) * 64, tid);

        const uint32_t sK = smb + (kt % AT_STAGES) * AT_STAGE;
        const uint32_t sV = sK + AT_TILE;

        // ---- S = Q K^T ----
        float c[8][4];
#pragma unroll
        for (int t = 0; t < 8; t++)
#pragma unroll
            for (int i = 0; i < 4; i++) c[t][i] = 0.0f;

#pragma unroll
        for (int ng = 0; ng < 4; ng++) {
#pragma unroll
            for (int kc = 0; kc < 4; kc++) {
                const uint32_t off = SWZ128(
                    (uint32_t)((ng * 16 + b_row) * 128 + kc * 32 + b_cb));
                uint32_t bh[4];
                LDSM_X4(bh[0], bh[1], bh[2], bh[3], sK + off);
                MMA_F16(c[2 * ng],     qh[kc], bh[0], bh[1]);
                MMA_F16(c[2 * ng + 1], qh[kc], bh[2], bh[3]);
            }
        }

        // ---- causal mask (boundary tiles only) ----
        const int kb = kt * 64;
        if (kb + 63 > r0) {
#pragma unroll
            for (int t = 0; t < 8; t++) {
                const int col = kb + t * 8 + 2 * (lane & 3);
                if (col > r0)         c[t][0] = -1e30f;
                if (col + 1 > r0)     c[t][1] = -1e30f;
                if (col > r0 + 8)     c[t][2] = -1e30f;
                if (col + 1 > r0 + 8) c[t][3] = -1e30f;
            }
        }

        // ---- online softmax ----
        float mx0 = -1e30f, mx1 = -1e30f;
#pragma unroll
        for (int t = 0; t < 8; t++) {
            mx0 = fmaxf(mx0, fmaxf(c[t][0], c[t][1]));
            mx1 = fmaxf(mx1, fmaxf(c[t][2], c[t][3]));
        }
        mx0 = fmaxf(mx0, __shfl_xor_sync(0xffffffffu, mx0, 1));
        mx0 = fmaxf(mx0, __shfl_xor_sync(0xffffffffu, mx0, 2));
        mx1 = fmaxf(mx1, __shfl_xor_sync(0xffffffffu, mx1, 1));
        mx1 = fmaxf(mx1, __shfl_xor_sync(0xffffffffu, mx1, 2));

        const float mn0 = fmaxf(m0, mx0);
        const float mn1 = fmaxf(m1, mx1);
        const float corr0 = __expf(m0 - mn0);
        const float corr1 = __expf(m1 - mn1);
        m0 = mn0; m1 = mn1;

        float rs0 = 0.0f, rs1 = 0.0f;
#pragma unroll
        for (int t = 0; t < 8; t++) {
            c[t][0] = __expf(c[t][0] - mn0); rs0 += c[t][0];
            c[t][1] = __expf(c[t][1] - mn0); rs0 += c[t][1];
            c[t][2] = __expf(c[t][2] - mn1); rs1 += c[t][2];
            c[t][3] = __expf(c[t][3] - mn1); rs1 += c[t][3];
        }
        rs0 += __shfl_xor_sync(0xffffffffu, rs0, 1);
        rs0 += __shfl_xor_sync(0xffffffffu, rs0, 2);
        rs1 += __shfl_xor_sync(0xffffffffu, rs1, 1);
        rs1 += __shfl_xor_sync(0xffffffffu, rs1, 2);
        l0 = l0 * corr0 + rs0;
        l1 = l1 * corr1 + rs1;

#pragma unroll
        for (int t = 0; t < 8; t++) {
            o[t][0] *= corr0; o[t][1] *= corr0;
            o[t][2] *= corr1; o[t][3] *= corr1;
        }

        // ---- O += P V, P packed fp16 in-register ----
#pragma unroll
        for (int kc = 0; kc < 4; kc++) {
            uint32_t ah[4];
            ah[0] = pack2h(c[2 * kc][0],     c[2 * kc][1]);
            ah[1] = pack2h(c[2 * kc][2],     c[2 * kc][3]);
            ah[2] = pack2h(c[2 * kc + 1][0], c[2 * kc + 1][1]);
            ah[3] = pack2h(c[2 * kc + 1][2], c[2 * kc + 1][3]);
#pragma unroll
            for (int ng = 0; ng < 4; ng++) {
                const uint32_t off = SWZ128(
                    (uint32_t)((kc * 16 + v_row) * 128 + ng * 32 + v_cb));
                uint32_t vh[4];
                LDSM_X4T(vh[0], vh[1], vh[2], vh[3], sV + off);
                MMA_F16(o[2 * ng],     ah, vh[0], vh[1]);
                MMA_F16(o[2 * ng + 1], ah, vh[2], vh[3]);
            }
        }
    }

    // ---- epilogue: normalize, fp16 ctx [L][N][E] ----
    const float inv0 = 1.0f / l0;
    const float inv1 = 1.0f / l1;
    const int nb = head >> 4;
    const int hh = head & 15;
    const size_t base0 =
        ((size_t)r0 * N_BATCH + nb) * EMB + hh * DH + 2 * (lane & 3);
    const size_t base1 = base0 + (size_t)8 * N_BATCH * EMB;
#pragma unroll
    for (int t = 0; t < 8; t++) {
        *(uint32_t*)(g_ctx16 + base0 + t * 8) =
            pack2h(o[t][0] * inv0, o[t][1] * inv0);
        *(uint32_t*)(g_ctx16 + base1 + t * 8) =
            pack2h(o[t][2] * inv1, o[t][3] * inv1);
    }
}

// ---------------------------------------------------------------------------
extern "C" void kernel_launch(void* const* d_in, const int* in_sizes, int n_in,
                              void* d_out, int out_size)
{
    const float* x    = (const float*)d_in[0];   // [L, N, E]
    const float* wqkv = (const float*)d_in[1];   // [3E, E]
    const float* wout = (const float*)d_in[2];   // [E, E]
    float* out = (float*)d_out;                  // [L, N, E]

    cudaFuncSetAttribute(tc_gemm_kernel,
                         cudaFuncAttributeMaxDynamicSharedMemorySize,
                         GEMM_SMEM_BYTES);
    cudaFuncSetAttribute(attn_hmma_kernel,
                         cudaFuncAttributeMaxDynamicSharedMemorySize,
                         ATTN_SMEM_BYTES);

    __half *x16, *w16, *o16, *ctx16;
    cudaGetSymbolAddress((void**)&x16, g_x16);
    cudaGetSymbolAddress((void**)&w16, g_wqkv16);
    cudaGetSymbolAddress((void**)&o16, g_wout16);
    cudaGetSymbolAddress((void**)&ctx16, g_ctx16);

    quant_all_kernel<<<1184, 256>>>(x, wqkv, wout);

    tc_gemm_kernel<<<dim3(24, 64), 256, GEMM_SMEM_BYTES>>>(
        x16, w16, nullptr, 0);

    attn_hmma_kernel<<<dim3(64, 16), 256, ATTN_SMEM_BYTES>>>();

    tc_gemm_kernel<<<dim3(8, 64), 256, GEMM_SMEM_BYTES>>>(
        ctx16, o16, out, 1);
}

// round 8
// speedup vs baseline: 8.8696x; 1.0738x over previous
#include <cuda_runtime.h>
#include <cuda_fp16.h>
#include <cstdint>
#include <math.h>

// Problem constants
#define L_SEQ   2048
#define N_BATCH 4
#define EMB     1024
#define NH      16
#define DH      64
#define NHEADS  (N_BATCH * NH)      // 64
#define M_ROWS  (L_SEQ * N_BATCH)   // 8192

// Q pre-scale: Dh^-0.5 * log2(e)  (softmax runs in log2 domain)
#define Q_SCALE 0.18033688011112042f

// ---------------------------------------------------------------------------
// Scratch (allocation-free: __device__ globals) — fp16 single-pass path
// ---------------------------------------------------------------------------
__device__ __half g_q16[(size_t)NHEADS * L_SEQ * DH];
__device__ __half g_k16[(size_t)NHEADS * L_SEQ * DH];
__device__ __half g_v16[(size_t)NHEADS * L_SEQ * DH];
__device__ __half g_x16[(size_t)M_ROWS * EMB];
__device__ __half g_wqkv16[(size_t)3 * EMB * EMB];
__device__ __half g_wout16[(size_t)EMB * EMB];
__device__ __half g_ctx16[(size_t)M_ROWS * EMB];

// ---------------------------------------------------------------------------
// PTX helpers (portable ISA: cp.async / ldmatrix / mma.sync)
// ---------------------------------------------------------------------------
__device__ __forceinline__ uint32_t smem_u32(const void* p) {
    uint32_t a;
    asm("{ .reg .u64 t; cvta.to.shared.u64 t, %1; cvt.u32.u64 %0, t; }"
        : "=r"(a) : "l"(p));
    return a;
}

#define SWZ128(o) ((o) ^ (((o) >> 3) & 0x70))

#define CP_ASYNC16(dst, src) \
    asm volatile("cp.async.cg.shared.global [%0], [%1], 16;" \
                 :: "r"(dst), "l"(src) : "memory")
#define CP_ASYNC_COMMIT()  asm volatile("cp.async.commit_group;" ::: "memory")
#define CP_ASYNC_WAIT(n)   asm volatile("cp.async.wait_group %0;" :: "n"(n) : "memory")

#define LDSM_X4(r0, r1, r2, r3, addr) \
    asm volatile("ldmatrix.sync.aligned.m8n8.x4.shared.b16 {%0,%1,%2,%3}, [%4];" \
                 : "=r"(r0), "=r"(r1), "=r"(r2), "=r"(r3) : "r"(addr))

#define LDSM_X4T(r0, r1, r2, r3, addr) \
    asm volatile("ldmatrix.sync.aligned.m8n8.x4.trans.shared.b16 {%0,%1,%2,%3}, [%4];" \
                 : "=r"(r0), "=r"(r1), "=r"(r2), "=r"(r3) : "r"(addr))

#define MMA_F16(c, a, b0, b1) \
    asm volatile("mma.sync.aligned.m16n8k16.row.col.f32.f16.f16.f32 " \
                 "{%0,%1,%2,%3}, {%4,%5,%6,%7}, {%8,%9}, {%0,%1,%2,%3};" \
                 : "+f"((c)[0]), "+f"((c)[1]), "+f"((c)[2]), "+f"((c)[3]) \
                 : "r"((a)[0]), "r"((a)[1]), "r"((a)[2]), "r"((a)[3]), \
                   "r"(b0), "r"(b1))

#define HALF2_ONES 0x3C003C00u   // {1.0h, 1.0h}

__device__ __forceinline__ uint32_t pack2h(float f0, float f1) {
    __half2 h = __floats2half2_rn(f0, f1);
    return *reinterpret_cast<uint32_t*>(&h);
}

// exp2 of two fp32 values -> packed fp16x2 (one MUFU op for both)
__device__ __forceinline__ uint32_t exp2_h2(float f0, float f1) {
    uint32_t r;
    asm("{\n\t.reg .b32 t;\n\t"
        "cvt.rn.f16x2.f32 t, %2, %1;\n\t"     // high=f1, low=f0
        "ex2.approx.f16x2 %0, t;\n\t}"
        : "=r"(r) : "f"(f0), "f"(f1));
    return r;
}

// ---------------------------------------------------------------------------
// Kernel 0: fused vectorized fp32 -> fp16 quantize of x, wqkv, wout
// ---------------------------------------------------------------------------
#define N_X   (M_ROWS * EMB)
#define N_WQ  (3 * EMB * EMB)
#define N_WO  (EMB * EMB)
#define N_ALL4 ((N_X + N_WQ + N_WO) / 4)

__global__ __launch_bounds__(256) void quant_all_kernel(
    const float* __restrict__ x, const float* __restrict__ wqkv,
    const float* __restrict__ wout)
{
    for (int i = blockIdx.x * blockDim.x + threadIdx.x; i < N_ALL4;
         i += gridDim.x * blockDim.x) {
        const int base = i * 4;
        const float* src;
        __half* dst;
        int off;
        if (base < N_X)             { src = x;    dst = g_x16;    off = base; }
        else if (base < N_X + N_WQ) { src = wqkv; dst = g_wqkv16; off = base - N_X; }
        else                        { src = wout; dst = g_wout16; off = base - N_X - N_WQ; }
        float4 v = *(const float4*)(src + off);
        uint2 h;
        h.x = pack2h(v.x, v.y);
        h.y = pack2h(v.z, v.w);
        *(uint2*)(dst + off) = h;
    }
}

// ---------------------------------------------------------------------------
// HMMA GEMM (fp16): C[m, o] = sum_k A[m,k] * B[o,k]
// CTA 128x128, K-chunk 64, 3-stage cp.async pipeline, warp tile 32x64.
// mode 0: QKV scatter epilogue (q scaled by Q_SCALE); mode 1: fp32 out rows
// ---------------------------------------------------------------------------
#define TILE_B 16384
#define STAGE_B (2 * TILE_B)
#define GEMM_STAGES 3
#define GEMM_SMEM_BYTES (GEMM_STAGES * STAGE_B)   // 96 KB

__device__ __forceinline__ void gemm_load_stage(
    uint32_t smst, const __half* A, const __half* B,
    int arow0, int brow0, int k0, int tid)
{
#pragma unroll
    for (int r = 0; r < 4; r++) {
        const int idx = r * 256 + tid;
        const int row = idx >> 3;
        const int cc = idx & 7;
        const uint32_t off = SWZ128((uint32_t)(row * 128 + cc * 16));
        CP_ASYNC16(smst + off, A + (size_t)(arow0 + row) * EMB + k0 + cc * 8);
        CP_ASYNC16(smst + TILE_B + off,
                   B + (size_t)(brow0 + row) * EMB + k0 + cc * 8);
    }
    CP_ASYNC_COMMIT();
}

__global__ __launch_bounds__(256, 2) void tc_gemm_kernel(
    const __half* __restrict__ A, const __half* __restrict__ B,
    float* __restrict__ out, int mode)
{
    extern __shared__ __align__(1024) char sm[];
    const uint32_t smb = smem_u32(sm);

    const int tid = threadIdx.x;
    const int wid = tid >> 5;
    const int lane = tid & 31;
    const int warp_m = wid & 3;
    const int warp_n = wid >> 2;
    const int bx = blockIdx.x;
    const int by = blockIdx.y;

    float c[2][8][4];
#pragma unroll
    for (int mt = 0; mt < 2; mt++)
#pragma unroll
        for (int nt = 0; nt < 8; nt++)
#pragma unroll
            for (int i = 0; i < 4; i++) c[mt][nt][i] = 0.0f;

    const int a_row = lane & 15;
    const int a_cb  = (lane >> 4) * 16;
    const int b_row = (lane & 7) + ((lane >> 4) << 3);
    const int b_cb  = ((lane >> 3) & 1) * 16;

    const int NCHUNK = EMB / 64;
    gemm_load_stage(smb, A, B, by * 128, bx * 128, 0, tid);
    gemm_load_stage(smb + STAGE_B, A, B, by * 128, bx * 128, 64, tid);

    for (int ck = 0; ck < NCHUNK; ck++) {
        if (ck + 1 < NCHUNK) { CP_ASYNC_WAIT(1); } else { CP_ASYNC_WAIT(0); }
        __syncthreads();
        if (ck + 2 < NCHUNK)
            gemm_load_stage(smb + ((ck + 2) % GEMM_STAGES) * STAGE_B, A, B,
                            by * 128, bx * 128, (ck + 2) * 64, tid);

        const uint32_t smA = smb + (ck % GEMM_STAGES) * STAGE_B;
        const uint32_t smB = smA + TILE_B;

#pragma unroll
        for (int ks = 0; ks < 4; ks++) {
            const int kbyte = ks * 32;
            uint32_t a[2][4];
#pragma unroll
            for (int mt = 0; mt < 2; mt++) {
                const uint32_t off = SWZ128(
                    (uint32_t)((warp_m * 32 + mt * 16 + a_row) * 128 + kbyte + a_cb));
                LDSM_X4(a[mt][0], a[mt][1], a[mt][2], a[mt][3], smA + off);
            }
#pragma unroll
            for (int np = 0; np < 4; np++) {
                const uint32_t off = SWZ128(
                    (uint32_t)((warp_n * 64 + np * 16 + b_row) * 128 + kbyte + b_cb));
                uint32_t bh[4];
                LDSM_X4(bh[0], bh[1], bh[2], bh[3], smB + off);
#pragma unroll
                for (int mt = 0; mt < 2; mt++) {
                    MMA_F16(c[mt][2 * np],     a[mt], bh[0], bh[1]);
                    MMA_F16(c[mt][2 * np + 1], a[mt], bh[2], bh[3]);
                }
            }
        }
    }

    // ---- epilogue ----
    const int mrow_base = by * 128 + warp_m * 32 + (lane >> 2);
    const int ncol_base = warp_n * 64 + 2 * (lane & 3);
#pragma unroll
    for (int mt = 0; mt < 2; mt++) {
#pragma unroll
        for (int half = 0; half < 2; half++) {
            const int m = mrow_base + mt * 16 + half * 8;
            if (mode == 0) {
                const int l = m >> 2;
                const int nb = m & 3;
                const int sec = bx >> 3;      // 0=q 1=k 2=v
#pragma unroll
                for (int nt = 0; nt < 8; nt++) {
                    const int o = bx * 128 + ncol_base + nt * 8;
                    const int h = (o & 1023) >> 6;
                    const int d = o & 63;
                    const size_t idx =
                        ((size_t)(nb * NH + h) * L_SEQ + l) * DH + d;
                    float v0 = c[mt][nt][half * 2];
                    float v1 = c[mt][nt][half * 2 + 1];
                    if (sec == 0) {
                        v0 *= Q_SCALE; v1 *= Q_SCALE;
                        *(uint32_t*)(g_q16 + idx) = pack2h(v0, v1);
                    } else if (sec == 1) {
                        *(uint32_t*)(g_k16 + idx) = pack2h(v0, v1);
                    } else {
                        *(uint32_t*)(g_v16 + idx) = pack2h(v0, v1);
                    }
                }
            } else {
                float* row = out + (size_t)m * EMB + bx * 128 + ncol_base;
#pragma unroll
                for (int nt = 0; nt < 8; nt++) {
                    float2 v = make_float2(c[mt][nt][half * 2],
                                           c[mt][nt][half * 2 + 1]);
                    *(float2*)(row + nt * 8) = v;
                }
            }
        }
    }
}

// ---------------------------------------------------------------------------
// Kernel 2: causal flash attention on fp16 HMMA, log2-domain softmax with
// fp16x2 ex2 and ones-MMA row sums. CTA = (head, 128 q rows), 8 warps,
// 64-key tiles, 3-stage pipeline, heaviest q-tiles first.
// ---------------------------------------------------------------------------
#define AT_TILE 8192
#define AT_STAGE (2 * AT_TILE)
#define AT_STAGES 3
#define ATTN_SMEM_BYTES (AT_STAGES * AT_STAGE)   // 48 KB

__device__ __forceinline__ void attn_load_stage(
    uint32_t smst, const __half* K, const __half* V, int kbase, int tid)
{
#pragma unroll
    for (int it = 0; it < 2; it++) {
        const int idx = it * 256 + tid;
        const int row = idx >> 3;
        const int cc = idx & 7;
        const uint32_t off = SWZ128((uint32_t)(row * 128 + cc * 16));
        CP_ASYNC16(smst + off, K + (size_t)(kbase + row) * DH + cc * 8);
        CP_ASYNC16(smst + AT_TILE + off,
                   V + (size_t)(kbase + row) * DH + cc * 8);
    }
    CP_ASYNC_COMMIT();
}

__global__ __launch_bounds__(256, 2) void attn_hmma_kernel()
{
    extern __shared__ __align__(1024) char sm[];
    const uint32_t smb = smem_u32(sm);

    const int tid = threadIdx.x;
    const int wid = tid >> 5;
    const int lane = tid & 31;
    const int head = blockIdx.x;
    const int bqt  = (int)gridDim.y - 1 - (int)blockIdx.y;  // heaviest first
    const int qbase = bqt * 128;

    const size_t hoff = (size_t)head * L_SEQ * DH;
    const __half* Q = g_q16 + hoff;
    const __half* K = g_k16 + hoff;
    const __half* V = g_v16 + hoff;

    const int r0 = qbase + wid * 16 + (lane >> 2);
    uint32_t qh[4][4];
#pragma unroll
    for (int kc = 0; kc < 4; kc++) {
        const int d0 = kc * 16 + 2 * (lane & 3);
        qh[kc][0] = *(const uint32_t*)(Q + (size_t)r0 * DH + d0);
        qh[kc][1] = *(const uint32_t*)(Q + (size_t)(r0 + 8) * DH + d0);
        qh[kc][2] = *(const uint32_t*)(Q + (size_t)r0 * DH + d0 + 8);
        qh[kc][3] = *(const uint32_t*)(Q + (size_t)(r0 + 8) * DH + d0 + 8);
    }

    float o[8][4];
#pragma unroll
    for (int t = 0; t < 8; t++)
#pragma unroll
        for (int i = 0; i < 4; i++) o[t][i] = 0.0f;
    float ol[4] = {0.0f, 0.0f, 0.0f, 0.0f};   // ones-MMA row-sum accumulator
    float m0 = -1e30f, m1 = -1e30f;

    const int b_row = (lane & 7) + ((lane >> 4) << 3);
    const int b_cb  = ((lane >> 3) & 1) * 16;
    const int v_row = ((lane >> 3) & 1) * 8 + (lane & 7);
    const int v_cb  = ((lane >> 4) & 1) * 16;

    const int nkt = qbase / 64 + 2;
    attn_load_stage(smb, K, V, 0, tid);
    if (nkt > 1) attn_load_stage(smb + AT_STAGE, K, V, 64, tid);

    for (int kt = 0; kt < nkt; kt++) {
        if (kt + 1 < nkt) { CP_ASYNC_WAIT(1); } else { CP_ASYNC_WAIT(0); }
        __syncthreads();
        if (kt + 2 < nkt)
            attn_load_stage(smb + ((kt + 2) % AT_STAGES) * AT_STAGE,
                            K, V, (kt + 2) * 64, tid);

        const uint32_t sK = smb + (kt % AT_STAGES) * AT_STAGE;
        const uint32_t sV = sK + AT_TILE;

        // ---- S = Q K^T (log2-domain: Q pre-scaled by Dh^-0.5 * log2e) ----
        float c[8][4];
#pragma unroll
        for (int t = 0; t < 8; t++)
#pragma unroll
            for (int i = 0; i < 4; i++) c[t][i] = 0.0f;

#pragma unroll
        for (int ng = 0; ng < 4; ng++) {
#pragma unroll
            for (int kc = 0; kc < 4; kc++) {
                const uint32_t off = SWZ128(
                    (uint32_t)((ng * 16 + b_row) * 128 + kc * 32 + b_cb));
                uint32_t bh[4];
                LDSM_X4(bh[0], bh[1], bh[2], bh[3], sK + off);
                MMA_F16(c[2 * ng],     qh[kc], bh[0], bh[1]);
                MMA_F16(c[2 * ng + 1], qh[kc], bh[2], bh[3]);
            }
        }

        // ---- causal mask (boundary tiles only) ----
        const int kb = kt * 64;
        if (kb + 63 > r0) {
#pragma unroll
            for (int t = 0; t < 8; t++) {
                const int col = kb + t * 8 + 2 * (lane & 3);
                if (col > r0)         c[t][0] = -1e30f;
                if (col + 1 > r0)     c[t][1] = -1e30f;
                if (col > r0 + 8)     c[t][2] = -1e30f;
                if (col + 1 > r0 + 8) c[t][3] = -1e30f;
            }
        }

        // ---- online softmax (log2 domain) ----
        float mx0 = -1e30f, mx1 = -1e30f;
#pragma unroll
        for (int t = 0; t < 8; t++) {
            mx0 = fmaxf(mx0, fmaxf(c[t][0], c[t][1]));
            mx1 = fmaxf(mx1, fmaxf(c[t][2], c[t][3]));
        }
        mx0 = fmaxf(mx0, __shfl_xor_sync(0xffffffffu, mx0, 1));
        mx0 = fmaxf(mx0, __shfl_xor_sync(0xffffffffu, mx0, 2));
        mx1 = fmaxf(mx1, __shfl_xor_sync(0xffffffffu, mx1, 1));
        mx1 = fmaxf(mx1, __shfl_xor_sync(0xffffffffu, mx1, 2));

        const float mn0 = fmaxf(m0, mx0);
        const float mn1 = fmaxf(m1, mx1);
        const float corr0 = exp2f(m0 - mn0);
        const float corr1 = exp2f(m1 - mn1);
        m0 = mn0; m1 = mn1;

        // p = exp2(c - m) in fp16x2 — directly the PV A-fragments
        uint32_t ph[4][4];
#pragma unroll
        for (int kc = 0; kc < 4; kc++) {
            ph[kc][0] = exp2_h2(c[2 * kc][0] - mn0,     c[2 * kc][1] - mn0);
            ph[kc][1] = exp2_h2(c[2 * kc][2] - mn1,     c[2 * kc][3] - mn1);
            ph[kc][2] = exp2_h2(c[2 * kc + 1][0] - mn0, c[2 * kc + 1][1] - mn0);
            ph[kc][3] = exp2_h2(c[2 * kc + 1][2] - mn1, c[2 * kc + 1][3] - mn1);
        }

#pragma unroll
        for (int t = 0; t < 8; t++) {
            o[t][0] *= corr0; o[t][1] *= corr0;
            o[t][2] *= corr1; o[t][3] *= corr1;
        }
        ol[0] *= corr0; ol[1] *= corr0;
        ol[2] *= corr1; ol[3] *= corr1;

        // ---- O += P V; l += P @ ones (tensor-core row sums) ----
#pragma unroll
        for (int kc = 0; kc < 4; kc++) {
#pragma unroll
            for (int ng = 0; ng < 4; ng++) {
                const uint32_t off = SWZ128(
                    (uint32_t)((kc * 16 + v_row) * 128 + ng * 32 + v_cb));
                uint32_t vh[4];
                LDSM_X4T(vh[0], vh[1], vh[2], vh[3], sV + off);
                MMA_F16(o[2 * ng],     ph[kc], vh[0], vh[1]);
                MMA_F16(o[2 * ng + 1], ph[kc], vh[2], vh[3]);
            }
            MMA_F16(ol, ph[kc], HALF2_ONES, HALF2_ONES);
        }
    }

    // ---- epilogue: normalize by ones-MMA row sums, fp16 ctx [L][N][E] ----
    const float inv0 = 1.0f / ol[0];
    const float inv1 = 1.0f / ol[2];
    const int nb = head >> 4;
    const int hh = head & 15;
    const size_t base0 =
        ((size_t)r0 * N_BATCH + nb) * EMB + hh * DH + 2 * (lane & 3);
    const size_t base1 = base0 + (size_t)8 * N_BATCH * EMB;
#pragma unroll
    for (int t = 0; t < 8; t++) {
        *(uint32_t*)(g_ctx16 + base0 + t * 8) =
            pack2h(o[t][0] * inv0, o[t][1] * inv0);
        *(uint32_t*)(g_ctx16 + base1 + t * 8) =
            pack2h(o[t][2] * inv1, o[t][3] * inv1);
    }
}

// ---------------------------------------------------------------------------
extern "C" void kernel_launch(void* const* d_in, const int* in_sizes, int n_in,
                              void* d_out, int out_size)
{
    const float* x    = (const float*)d_in[0];
    const float* wqkv = (const float*)d_in[1];
    const float* wout = (const float*)d_in[2];
    float* out = (float*)d_out;

    cudaFuncSetAttribute(tc_gemm_kernel,
                         cudaFuncAttributeMaxDynamicSharedMemorySize,
                         GEMM_SMEM_BYTES);
    cudaFuncSetAttribute(attn_hmma_kernel,
                         cudaFuncAttributeMaxDynamicSharedMemorySize,
                         ATTN_SMEM_BYTES);

    __half *x16, *w16, *o16, *ctx16;
    cudaGetSymbolAddress((void**)&x16, g_x16);
    cudaGetSymbolAddress((void**)&w16, g_wqkv16);
    cudaGetSymbolAddress((void**)&o16, g_wout16);
    cudaGetSymbolAddress((void**)&ctx16, g_ctx16);

    quant_all_kernel<<<592, 256>>>(x, wqkv, wout);

    tc_gemm_kernel<<<dim3(24, 64), 256, GEMM_SMEM_BYTES>>>(
        x16, w16, nullptr, 0);

    attn_hmma_kernel<<<dim3(64, 16), 256, ATTN_SMEM_BYTES>>>();

    tc_gemm_kernel<<<dim3(8, 64), 256, GEMM_SMEM_BYTES>>>(
        ctx16, o16, out, 1);
}